// round 13
// baseline (speedup 1.0000x reference)
#include <cuda_runtime.h>
#include <cstdint>

typedef unsigned int u32;
typedef signed char  s8;
typedef unsigned char u8;

#define HW    3136            // 56*56
#define NPIX  100352          // 32*3136
#define CIN   64
#define PEXP  384
#define COUT  96

// ---------------- device scratch ----------------
static __device__ __align__(16) s8    g_xq [(size_t)NPIX * CIN];     // x int4 codes, NHWC
static __device__ __align__(16) u8    g_o1 [(size_t)NPIX * PEXP];    // stage1 codes -> mapped int8
static __device__ __align__(16) u8    g_o2 [(size_t)NPIX * PEXP];    // stage2 codes -> mapped int8
static __device__ __align__(16) short g_acc3[(size_t)32 * COUT * HW]; // conv3 raw int acc, NCHW
static __device__ __align__(16) short g_accS[(size_t)32 * COUT * HW]; // shortcut raw int acc, NCHW
static __device__ __align__(16) s8    g_w1q[PEXP * CIN];
static __device__ __align__(16) s8    g_w2q[9 * PEXP];               // [tap][384]
static __device__ __align__(16) s8    g_w3q[COUT * PEXP];
static __device__ __align__(16) s8    g_wsq[COUT * CIN];
static __device__ float g_inv1[PEXP], g_add1[PEXP], g_inv2[PEXP], g_add2[PEXP];
static __device__ float g_inv3[COUT], g_add3[COUT], g_invS[COUT], g_addS[COUT];
static __device__ u32   g_maxx_bits;
static __device__ int   g_max_o1, g_max_o2, g_max_a3, g_max_aS;
static __device__ float g_sx, g_sxinv;
static __device__ float g_sw[4];                 // s_w1, s_w2, s_w3, s_ws
static __device__ int   g_lut2[16], g_lut3[16];
static __device__ float g_s2prod, g_s3prod;      // input_scale * weight_scale
static __device__ float g_r3, g_sO, g_rS, g_sS;  // final requant factors

// ---------------- helpers ----------------
__device__ __forceinline__ float pow2ceil(float q) {
    // exact exp2(ceil(log2(q))), q > 0
    int e; float f = frexpf(q, &e);     // q = f * 2^e, f in [0.5, 1)
    if (f == 0.5f) e -= 1;
    return ldexpf(1.0f, e);
}
__device__ __forceinline__ int clampi(int v, int lo, int hi) {
    return min(max(v, lo), hi);
}
__device__ __forceinline__ int wredmax(int v) {
    #pragma unroll
    for (int o = 16; o; o >>= 1) v = max(v, __shfl_xor_sync(0xffffffffu, v, o));
    return v;
}

// ---------------- K0: reset atomics ----------------
__global__ void k_reset() {
    if (threadIdx.x == 0) {
        g_maxx_bits = 0u; g_max_o1 = 0; g_max_o2 = 0; g_max_a3 = 0; g_max_aS = 0;
    }
}

// ---------------- K1: max|x| ----------------
__global__ __launch_bounds__(256) void k_maxx(const float* __restrict__ x) {
    __shared__ float sred[8];
    float mx = 0.f;
    const int n4 = (32 * CIN * HW) / 4;
    for (int i = blockIdx.x * blockDim.x + threadIdx.x; i < n4; i += gridDim.x * blockDim.x) {
        float4 v = ((const float4*)x)[i];
        mx = fmaxf(mx, fmaxf(fmaxf(fabsf(v.x), fabsf(v.y)), fmaxf(fabsf(v.z), fabsf(v.w))));
    }
    #pragma unroll
    for (int o = 16; o; o >>= 1) mx = fmaxf(mx, __shfl_xor_sync(0xffffffffu, mx, o));
    if ((threadIdx.x & 31) == 0) sred[threadIdx.x >> 5] = mx;
    __syncthreads();
    if (threadIdx.x == 0) {
        float m = sred[0];
        #pragma unroll
        for (int w = 1; w < 8; w++) m = fmaxf(m, sred[w]);
        atomicMax(&g_maxx_bits, __float_as_uint(m));
    }
}

// ---------------- K2: weight quant + BN folds + s_x ----------------
__global__ __launch_bounds__(256) void k_prep(
    const float* __restrict__ w1, const float* __restrict__ w2,
    const float* __restrict__ w3, const float* __restrict__ ws,
    const float* __restrict__ g1, const float* __restrict__ b1,
    const float* __restrict__ m1, const float* __restrict__ v1,
    const float* __restrict__ g2, const float* __restrict__ b2,
    const float* __restrict__ m2, const float* __restrict__ v2,
    const float* __restrict__ g3, const float* __restrict__ b3,
    const float* __restrict__ m3, const float* __restrict__ v3,
    const float* __restrict__ gs, const float* __restrict__ bs,
    const float* __restrict__ ms, const float* __restrict__ vs) {
    const int blk = blockIdx.x, t = threadIdx.x;
    if (blk < 4) {
        const float* w; int n; s8* dst;
        if (blk == 0)      { w = w1; n = PEXP * CIN;  dst = g_w1q; }
        else if (blk == 1) { w = w2; n = PEXP * 9;    dst = g_w2q; }
        else if (blk == 2) { w = w3; n = COUT * PEXP; dst = g_w3q; }
        else               { w = ws; n = COUT * CIN;  dst = g_wsq; }
        __shared__ float sred[256];
        __shared__ float s_si;
        float mx = 0.f;
        for (int i = t; i < n; i += 256) mx = fmaxf(mx, fabsf(w[i]));
        sred[t] = mx; __syncthreads();
        for (int s = 128; s > 0; s >>= 1) {
            if (t < s) sred[t] = fmaxf(sred[t], sred[t + s]);
            __syncthreads();
        }
        if (t == 0) {
            float m = fmaxf(sred[0], 1e-8f);
            float s = pow2ceil(__fdiv_rn(m, 7.0f));
            g_sw[blk] = s; s_si = 1.0f / s;
        }
        __syncthreads();
        float si = s_si;
        for (int i = t; i < n; i += 256) {
            float r = fminf(fmaxf(rintf(__fmul_rn(w[i], si)), -8.f), 7.f);
            if (blk == 1) { int p = i / 9, tap = i % 9; g_w2q[tap * PEXP + p] = (s8)(int)r; }
            else dst[i] = (s8)(int)r;
        }
    } else if (blk == 4) {
        for (int c = t; c < PEXP; c += 256) {
            float inv = __fmul_rn(g1[c], 1.0f / sqrtf(v1[c] + 1e-5f));
            g_inv1[c] = inv; g_add1[c] = __fsub_rn(b1[c], __fmul_rn(m1[c], inv));
        }
    } else if (blk == 5) {
        for (int c = t; c < PEXP; c += 256) {
            float inv = __fmul_rn(g2[c], 1.0f / sqrtf(v2[c] + 1e-5f));
            g_inv2[c] = inv; g_add2[c] = __fsub_rn(b2[c], __fmul_rn(m2[c], inv));
        }
    } else if (blk == 6) {
        for (int c = t; c < COUT; c += 256) {
            float inv = __fmul_rn(g3[c], 1.0f / sqrtf(v3[c] + 1e-5f));
            g_inv3[c] = inv; g_add3[c] = __fsub_rn(b3[c], __fmul_rn(m3[c], inv));
            float invs = __fmul_rn(gs[c], 1.0f / sqrtf(vs[c] + 1e-5f));
            g_invS[c] = invs; g_addS[c] = __fsub_rn(bs[c], __fmul_rn(ms[c], invs));
        }
    } else {
        if (t == 0) {
            float m = fmaxf(__uint_as_float(g_maxx_bits), 1e-8f);
            float s = pow2ceil(__fdiv_rn(m, 7.0f));
            g_sx = s; g_sxinv = 1.0f / s;
        }
    }
}

// ---------------- K3: quantize x, NCHW f32 -> NHWC int8 codes ----------------
__global__ __launch_bounds__(256) void k_qx(const float* __restrict__ x) {
    __shared__ s8 sm[64 * 68];
    const int b = blockIdx.x / 49;
    const int pix0 = (blockIdx.x % 49) * 64;          // within-image pixel base
    const int t = threadIdx.x;
    const float sxinv = g_sxinv;
    const int px = t & 63, cg = t >> 6;
    #pragma unroll
    for (int j = 0; j < 16; j++) {
        int c = cg * 16 + j;
        float v = x[(size_t)(b * CIN + c) * HW + pix0 + px];
        float q = fminf(fmaxf(rintf(__fmul_rn(v, sxinv)), -8.f), 7.f);
        sm[px * 68 + c] = (s8)(int)q;
    }
    __syncthreads();
    const int pix = t >> 2, cofs = (t & 3) * 16;
    const int* sp = (const int*)(sm + pix * 68 + cofs);
    int4 v = make_int4(sp[0], sp[1], sp[2], sp[3]);
    ((int4*)g_xq)[(size_t)(b * HW + pix0 + pix) * 4 + (t & 3)] = v;
}

// ---------------- K4: conv1 1x1 (64->384) + BN + relu4 ----------------
__global__ __launch_bounds__(256) void k_conv1() {
    __shared__ int xs[128 * 17];
    __shared__ int ws[64 * 17];
    __shared__ int s_wmax[8];
    const int pix0 = blockIdx.x * 128;
    const int p0   = blockIdx.y * 64;
    const int t = threadIdx.x;
    const int* xg = (const int*)g_xq;
    const int* wg = (const int*)g_w1q;
    #pragma unroll
    for (int i = t; i < 128 * 16; i += 256) xs[(i >> 4) * 17 + (i & 15)] = xg[pix0 * 16 + i];
    #pragma unroll
    for (int i = t; i < 64 * 16; i += 256)  ws[(i >> 4) * 17 + (i & 15)] = wg[p0 * 16 + i];
    __syncthreads();
    int acc[8][4] = {};
    const int pi = t & 15, pj = t >> 4;
    #pragma unroll 8
    for (int k = 0; k < 16; k++) {
        int a[8], bb[4];
        #pragma unroll
        for (int i = 0; i < 8; i++) a[i] = xs[(pi + 16 * i) * 17 + k];
        #pragma unroll
        for (int j = 0; j < 4; j++) bb[j] = ws[(pj + 16 * j) * 17 + k];
        #pragma unroll
        for (int i = 0; i < 8; i++)
            #pragma unroll
            for (int j = 0; j < 4; j++)
                acc[i][j] = __dp4a(a[i], bb[j], acc[i][j]);
    }
    const float sc = __fmul_rn(g_sx, g_sw[0]);
    float inv[4], add[4];
    #pragma unroll
    for (int j = 0; j < 4; j++) { int p = p0 + pj + 16 * j; inv[j] = g_inv1[p]; add[j] = g_add1[p]; }
    __syncthreads();                       // xs reads done -> reuse as staging
    u8* so = (u8*)xs;                      // 128*64 = 8192B <= 8704B
    int mymax = 0;
    #pragma unroll
    for (int i = 0; i < 8; i++)
        #pragma unroll
        for (int j = 0; j < 4; j++) {
            float raw = __fmul_rn(__int2float_rn(acc[i][j]), sc);
            float y = __fadd_rn(__fmul_rn(raw, inv[j]), add[j]);
            int code = clampi((int)rintf(__fmul_rn(y, 4.0f)), 0, 15);
            mymax = max(mymax, code);
            so[(pi + 16 * i) * 64 + (pj + 16 * j)] = (u8)code;
        }
    mymax = wredmax(mymax);
    if ((t & 31) == 0) s_wmax[t >> 5] = mymax;
    __syncthreads();
    const int4* s4 = (const int4*)so;
    #pragma unroll
    for (int i = t; i < 512; i += 256) {
        int pix = i >> 2, c16 = i & 3;
        ((int4*)g_o1)[(size_t)(pix0 + pix) * 24 + (p0 >> 4) + c16] = s4[i];
    }
    if (t == 0) {
        int m = s_wmax[0];
        #pragma unroll
        for (int w = 1; w < 8; w++) m = max(m, s_wmax[w]);
        atomicMax(&g_max_o1, m);
    }
}

// ---------------- K5/K7: requant LUT for next stage ----------------
__global__ void k_lut(int which) {
    if (threadIdx.x == 0) {
        int mc = which ? g_max_o2 : g_max_o1;
        float m = fmaxf(__fmul_rn((float)mc, 0.25f), 1e-8f);
        float s = pow2ceil(__fdiv_rn(m, 7.0f));
        float si = 1.0f / s;
        for (int c = 0; c < 16; c++) {
            float q = rintf(__fmul_rn(__fmul_rn((float)c, 0.25f), si));
            int v = (int)fminf(fmaxf(q, -8.f), 7.f);
            if (which) g_lut3[c] = v; else g_lut2[c] = v;
        }
        if (which) g_s3prod = __fmul_rn(s, g_sw[2]);
        else       g_s2prod = __fmul_rn(s, g_sw[1]);
    }
}

// ---------------- K5b/K7b: apply LUT in place ----------------
__global__ __launch_bounds__(256) void k_map(int which) {
    __shared__ s8 sl[16];
    if (threadIdx.x < 16) sl[threadIdx.x] = (s8)(which ? g_lut3[threadIdx.x] : g_lut2[threadIdx.x]);
    __syncthreads();
    int4* buf = which ? (int4*)g_o2 : (int4*)g_o1;
    const int n4 = (int)(((size_t)NPIX * PEXP) / 16);
    for (int i = blockIdx.x * blockDim.x + threadIdx.x; i < n4; i += gridDim.x * blockDim.x) {
        int4 v = buf[i];
        int* w = (int*)&v;
        #pragma unroll
        for (int q = 0; q < 4; q++) {
            u32 x = (u32)w[q], r = 0;
            r |= (u32)(u8)sl[x & 15];
            r |= (u32)(u8)sl[(x >> 8) & 15] << 8;
            r |= (u32)(u8)sl[(x >> 16) & 15] << 16;
            r |= (u32)(u8)sl[(x >> 24) & 15] << 24;
            w[q] = (int)r;
        }
        buf[i] = v;
    }
}

// ---------------- K6: depthwise 3x3 + BN + relu4 ----------------
__global__ __launch_bounds__(384) void k_conv2() {
    __shared__ s8 sm[10 * 10 * PEXP];      // 38400 B
    __shared__ int s_wmax[12];
    const int b = blockIdx.x / 49;
    const int tile = blockIdx.x % 49;
    const int oy0 = (tile / 7) * 8, ox0 = (tile % 7) * 8;
    const int t = threadIdx.x;
    for (int idx = t; idx < 2400; idx += 384) {
        int cell = idx / 24, c16 = idx % 24;
        int iy = oy0 - 1 + cell / 10, ix = ox0 - 1 + cell % 10;
        int4 v = make_int4(0, 0, 0, 0);
        if (iy >= 0 && iy < 56 && ix >= 0 && ix < 56)
            v = ((const int4*)g_o1)[(size_t)(b * HW + iy * 56 + ix) * 24 + c16];
        ((int4*)sm)[cell * 24 + c16] = v;
    }
    __syncthreads();
    const int c4 = t % 96, strip = t / 96;
    int wv[9];
    #pragma unroll
    for (int tap = 0; tap < 9; tap++) wv[tap] = ((const int*)g_w2q)[tap * 96 + c4];
    float inv[4], add[4];
    #pragma unroll
    for (int l = 0; l < 4; l++) { int c = c4 * 4 + l; inv[l] = g_inv2[c]; add[l] = g_add2[c]; }
    const float s2p = g_s2prod;
    int mymax = 0;
    #pragma unroll
    for (int sub = 0; sub < 4; sub++) {
        int base[4], oyv[4], oxv[4];
        #pragma unroll
        for (int k = 0; k < 4; k++) {
            int pix = strip * 16 + sub * 4 + k;
            int oy = pix >> 3, ox = pix & 7;
            oyv[k] = oy; oxv[k] = ox;
            base[k] = (oy * 10 + ox) * PEXP + c4 * 4;
        }
        int acc[4][4] = {};
        #pragma unroll
        for (int dy = 0; dy < 3; dy++)
            #pragma unroll
            for (int dx = 0; dx < 3; dx++) {
                int w = wv[dy * 3 + dx];
                int w0 = (w << 24) >> 24, w1 = (w << 16) >> 24, w2 = (w << 8) >> 24, w3 = w >> 24;
                int toff = (dy * 10 + dx) * PEXP;
                #pragma unroll
                for (int k = 0; k < 4; k++) {
                    int v = *(const int*)(sm + base[k] + toff);
                    acc[k][0] += ((v << 24) >> 24) * w0;
                    acc[k][1] += ((v << 16) >> 24) * w1;
                    acc[k][2] += ((v << 8) >> 24) * w2;
                    acc[k][3] += (v >> 24) * w3;
                }
            }
        #pragma unroll
        for (int k = 0; k < 4; k++) {
            u32 pk = 0;
            #pragma unroll
            for (int l = 0; l < 4; l++) {
                float raw = __fmul_rn(__int2float_rn(acc[k][l]), s2p);
                float y = __fadd_rn(__fmul_rn(raw, inv[l]), add[l]);
                int code = clampi((int)rintf(__fmul_rn(y, 4.0f)), 0, 15);
                mymax = max(mymax, code);
                pk |= (u32)code << (8 * l);
            }
            // FIXED: add tile origin (oy0, ox0) to the output address
            *(u32*)(g_o2 + (size_t)(b * HW + (oy0 + oyv[k]) * 56 + (ox0 + oxv[k])) * PEXP + c4 * 4) = pk;
        }
    }
    mymax = wredmax(mymax);
    if ((t & 31) == 0) s_wmax[t >> 5] = mymax;
    __syncthreads();
    if (t == 0) {
        int m = s_wmax[0];
        #pragma unroll
        for (int w = 1; w < 12; w++) m = max(m, s_wmax[w]);
        atomicMax(&g_max_o2, m);
    }
}

// ---------------- K8: conv3 1x1 (384->96) -> int16 raw acc + |max| ----------------
__global__ __launch_bounds__(256) void k_conv3() {
    __shared__ int xs[64 * 49];
    __shared__ int ws[96 * 49];
    __shared__ short ss[96 * 64];
    __shared__ int s_wmax[8];
    const int pix0 = blockIdx.x * 64;
    const int t = threadIdx.x;
    const int* xg = (const int*)g_o2;
    const int* wg = (const int*)g_w3q;
    const int pi = t & 15, pj = t >> 4;
    int acc[4][6] = {};
    #pragma unroll
    for (int kc = 0; kc < 2; kc++) {
        for (int i = t; i < 64 * 48; i += 256) {
            int pix = i / 48, k = i % 48;
            xs[pix * 49 + k] = xg[(pix0 + pix) * 96 + kc * 48 + k];
        }
        for (int i = t; i < 96 * 48; i += 256) {
            int o = i / 48, k = i % 48;
            ws[o * 49 + k] = wg[o * 96 + kc * 48 + k];
        }
        __syncthreads();
        #pragma unroll 6
        for (int k = 0; k < 48; k++) {
            int a[4], bb[6];
            #pragma unroll
            for (int i = 0; i < 4; i++) a[i] = xs[(pi + 16 * i) * 49 + k];
            #pragma unroll
            for (int j = 0; j < 6; j++) bb[j] = ws[(pj + 16 * j) * 49 + k];
            #pragma unroll
            for (int i = 0; i < 4; i++)
                #pragma unroll
                for (int j = 0; j < 6; j++)
                    acc[i][j] = __dp4a(a[i], bb[j], acc[i][j]);
        }
        __syncthreads();
    }
    int amax = 0;
    #pragma unroll
    for (int i = 0; i < 4; i++)
        #pragma unroll
        for (int j = 0; j < 6; j++) {
            int a = acc[i][j];
            amax = max(amax, abs(a));
            ss[(pj + 16 * j) * 64 + (pi + 16 * i)] = (short)a;
        }
    amax = wredmax(amax);
    if ((t & 31) == 0) s_wmax[t >> 5] = amax;
    __syncthreads();
    const int bimg = pix0 / HW, hw0 = pix0 % HW;
    const int4* s4 = (const int4*)ss;
    #pragma unroll
    for (int i = t; i < 768; i += 256) {
        int o = i >> 3, seg = i & 7;
        ((int4*)g_acc3)[(size_t)(bimg * COUT + o) * 392 + (hw0 >> 3) + seg] = s4[i];
    }
    if (t == 0) {
        int m = s_wmax[0];
        #pragma unroll
        for (int w = 1; w < 8; w++) m = max(m, s_wmax[w]);
        atomicMax(&g_max_a3, m);
    }
}

// ---------------- K8b: shortcut 1x1 (64->96) -> int16 raw acc + |max| ----------------
__global__ __launch_bounds__(256) void k_convS() {
    __shared__ int xs[64 * 17];
    __shared__ int ws[96 * 17];
    __shared__ short ss[96 * 64];
    __shared__ int s_wmax[8];
    const int pix0 = blockIdx.x * 64;
    const int t = threadIdx.x;
    const int* xg = (const int*)g_xq;
    const int* wg = (const int*)g_wsq;
    #pragma unroll
    for (int i = t; i < 64 * 16; i += 256) xs[(i >> 4) * 17 + (i & 15)] = xg[pix0 * 16 + i];
    #pragma unroll
    for (int i = t; i < 96 * 16; i += 256) ws[(i >> 4) * 17 + (i & 15)] = wg[i];
    __syncthreads();
    const int pi = t & 15, pj = t >> 4;
    int acc[4][6] = {};
    #pragma unroll
    for (int k = 0; k < 16; k++) {
        int a[4], bb[6];
        #pragma unroll
        for (int i = 0; i < 4; i++) a[i] = xs[(pi + 16 * i) * 17 + k];
        #pragma unroll
        for (int j = 0; j < 6; j++) bb[j] = ws[(pj + 16 * j) * 17 + k];
        #pragma unroll
        for (int i = 0; i < 4; i++)
            #pragma unroll
            for (int j = 0; j < 6; j++)
                acc[i][j] = __dp4a(a[i], bb[j], acc[i][j]);
    }
    int amax = 0;
    #pragma unroll
    for (int i = 0; i < 4; i++)
        #pragma unroll
        for (int j = 0; j < 6; j++) {
            int a = acc[i][j];
            amax = max(amax, abs(a));
            ss[(pj + 16 * j) * 64 + (pi + 16 * i)] = (short)a;
        }
    amax = wredmax(amax);
    if ((t & 31) == 0) s_wmax[t >> 5] = amax;
    __syncthreads();
    const int bimg = pix0 / HW, hw0 = pix0 % HW;
    const int4* s4 = (const int4*)ss;
    #pragma unroll
    for (int i = t; i < 768; i += 256) {
        int o = i >> 3, seg = i & 7;
        ((int4*)g_accS)[(size_t)(bimg * COUT + o) * 392 + (hw0 >> 3) + seg] = s4[i];
    }
    if (t == 0) {
        int m = s_wmax[0];
        #pragma unroll
        for (int w = 1; w < 8; w++) m = max(m, s_wmax[w]);
        atomicMax(&g_max_aS, m);
    }
}

// ---------------- K9: final requant scales ----------------
__global__ void k_scales() {
    if (threadIdx.x == 0) {
        float m3 = fmaxf(__fmul_rn(g_s3prod, (float)g_max_a3), 1e-8f);
        float sO = pow2ceil(__fdiv_rn(m3, 127.0f));
        g_r3 = __fdiv_rn(g_s3prod, sO); g_sO = sO;     // exact pow2 ratio
        float sxw = __fmul_rn(g_sx, g_sw[3]);
        float mS = fmaxf(__fmul_rn(sxw, (float)g_max_aS), 1e-8f);
        float sS = pow2ceil(__fdiv_rn(mS, 7.0f));
        g_rS = __fdiv_rn(sxw, sS); g_sS = sS;
    }
}

// ---------------- K10: fused epilogue -> output (NCHW f32) ----------------
__global__ __launch_bounds__(256) void k_epi(float* __restrict__ out) {
    const float r3 = g_r3, sO = g_sO, rS = g_rS, sS = g_sS;
    const int n8 = (32 * COUT * HW) / 8;   // 1204224
    for (int i = blockIdx.x * blockDim.x + threadIdx.x; i < n8; i += gridDim.x * blockDim.x) {
        int c = (i / 392) % COUT;
        float inv3 = g_inv3[c], add3 = g_add3[c], invS = g_invS[c], addS = g_addS[c];
        int4 av = ((const int4*)g_acc3)[i];
        int4 sv = ((const int4*)g_accS)[i];
        const short* ap = (const short*)&av;
        const short* sp = (const short*)&sv;
        float r[8];
        #pragma unroll
        for (int l = 0; l < 8; l++) {
            float q3 = fminf(fmaxf(rintf(__fmul_rn((float)ap[l], r3)), -128.f), 127.f);
            float y3 = __fadd_rn(__fmul_rn(__fmul_rn(q3, sO), inv3), add3);
            float qS = fminf(fmaxf(rintf(__fmul_rn((float)sp[l], rS)), -8.f), 7.f);
            float yS = __fadd_rn(__fmul_rn(__fmul_rn(qS, sS), invS), addS);
            float sum = __fadd_rn(y3, yS);
            float code = fminf(fmaxf(rintf(__fmul_rn(sum, 4.0f)), 0.f), 15.f);
            r[l] = __fmul_rn(code, 0.25f);
        }
        float4* o4 = (float4*)out;
        o4[(size_t)i * 2]     = make_float4(r[0], r[1], r[2], r[3]);
        o4[(size_t)i * 2 + 1] = make_float4(r[4], r[5], r[6], r[7]);
    }
}

// ---------------- launch ----------------
extern "C" void kernel_launch(void* const* d_in, const int* in_sizes, int n_in,
                              void* d_out, int out_size) {
    const float* x  = (const float*)d_in[0];
    const float* w1 = (const float*)d_in[1];
    const float* g1 = (const float*)d_in[2];
    const float* b1 = (const float*)d_in[3];
    const float* m1 = (const float*)d_in[4];
    const float* v1 = (const float*)d_in[5];
    const float* w2 = (const float*)d_in[6];
    const float* g2 = (const float*)d_in[7];
    const float* b2 = (const float*)d_in[8];
    const float* m2 = (const float*)d_in[9];
    const float* v2 = (const float*)d_in[10];
    const float* w3 = (const float*)d_in[11];
    const float* g3 = (const float*)d_in[12];
    const float* b3 = (const float*)d_in[13];
    const float* m3 = (const float*)d_in[14];
    const float* v3 = (const float*)d_in[15];
    const float* ws = (const float*)d_in[16];
    const float* gs = (const float*)d_in[17];
    const float* bs = (const float*)d_in[18];
    const float* ms = (const float*)d_in[19];
    const float* vs = (const float*)d_in[20];

    k_reset<<<1, 32>>>();
    k_maxx<<<512, 256>>>(x);
    k_prep<<<8, 256>>>(w1, w2, w3, ws, g1, b1, m1, v1, g2, b2, m2, v2,
                       g3, b3, m3, v3, gs, bs, ms, vs);
    k_qx<<<1568, 256>>>(x);
    k_conv1<<<dim3(784, 6), 256>>>();
    k_lut<<<1, 32>>>(0);
    k_map<<<2048, 256>>>(0);
    k_conv2<<<1568, 384>>>();
    k_lut<<<1, 32>>>(1);
    k_map<<<2048, 256>>>(1);
    k_conv3<<<1568, 256>>>();
    k_convS<<<1568, 256>>>();
    k_scales<<<1, 32>>>();
    k_epi<<<4704, 256>>>((float*)d_out);
}

// round 14
// speedup vs baseline: 1.5509x; 1.5509x over previous
#include <cuda_runtime.h>
#include <cstdint>

typedef unsigned int u32;
typedef signed char  s8;
typedef unsigned char u8;

#define HW    3136            // 56*56
#define NPIX  100352          // 32*3136
#define CIN   64
#define PEXP  384
#define COUT  96

// ---------------- device scratch ----------------
static __device__ __align__(16) s8    g_xq [(size_t)NPIX * CIN];     // x int4 codes, NHWC
static __device__ __align__(16) u8    g_o1 [(size_t)NPIX * PEXP];    // stage1 relu4 codes 0..15
static __device__ __align__(16) u8    g_o2 [(size_t)NPIX * PEXP];    // stage2 relu4 codes 0..15
static __device__ __align__(16) short g_acc3[(size_t)32 * COUT * HW]; // conv3 raw int acc, NCHW
static __device__ __align__(16) short g_accS[(size_t)32 * COUT * HW]; // shortcut raw int acc, NCHW
static __device__ __align__(16) s8    g_w1q[PEXP * CIN];
static __device__ __align__(16) s8    g_w2q[9 * PEXP];               // [tap][384]
static __device__ __align__(16) s8    g_w3q[COUT * PEXP];
static __device__ __align__(16) s8    g_wsq[COUT * CIN];
static __device__ float g_inv1[PEXP], g_add1[PEXP], g_inv2[PEXP], g_add2[PEXP];
static __device__ float g_inv3[COUT], g_add3[COUT], g_invS[COUT], g_addS[COUT];
static __device__ u32   g_maxx_bits;
static __device__ int   g_max_o1, g_max_o2, g_max_a3, g_max_aS;
static __device__ float g_sx, g_sxinv;
static __device__ float g_sw[4];                 // s_w1, s_w2, s_w3, s_ws
static __device__ float g_r3, g_sO, g_rS, g_sS;  // final requant factors

// ---------------- helpers ----------------
__device__ __forceinline__ float pow2ceil(float q) {
    // exact exp2(ceil(log2(q))), q > 0
    int e; float f = frexpf(q, &e);     // q = f * 2^e, f in [0.5, 1)
    if (f == 0.5f) e -= 1;
    return ldexpf(1.0f, e);
}
__device__ __forceinline__ int clampi(int v, int lo, int hi) {
    return min(max(v, lo), hi);
}
__device__ __forceinline__ int wredmax(int v) {
    #pragma unroll
    for (int o = 16; o; o >>= 1) v = max(v, __shfl_xor_sync(0xffffffffu, v, o));
    return v;
}

// Build 256-entry byte-pair requant LUT in shared from a max-code value.
// Entry [c1*16+c0] = mapped(c0) | mapped(c1)<<8 ; mapped(c) in 0..7 (never negative).
// Must be called by threads t<256; caller syncs afterwards.
__device__ __forceinline__ void build_pairlut(u32* slut2, int t, int maxcode) {
    float m = fmaxf(__fmul_rn((float)maxcode, 0.25f), 1e-8f);
    float s = pow2ceil(__fdiv_rn(m, 7.0f));
    float si = 1.0f / s;
    if (t < 256) {
        int c0 = t & 15, c1 = t >> 4;
        int v0 = (int)fminf(fmaxf(rintf(__fmul_rn(__fmul_rn((float)c0, 0.25f), si)), -8.f), 7.f);
        int v1 = (int)fminf(fmaxf(rintf(__fmul_rn(__fmul_rn((float)c1, 0.25f), si)), -8.f), 7.f);
        slut2[t] = (u32)(v0 | (v1 << 8));
    }
}

// Map one word of 4 codes (each byte 0..15) through the pair LUT.
__device__ __forceinline__ u32 map_word(u32 w, const u32* slut2) {
    u32 i0 = (w & 15u) | ((w >> 4) & 0xF0u);
    u32 i1 = ((w >> 16) & 15u) | ((w >> 20) & 0xF0u);
    return slut2[i0] | (slut2[i1] << 16);
}
__device__ __forceinline__ int4 map_int4(int4 v, const u32* slut2) {
    int4 r;
    r.x = (int)map_word((u32)v.x, slut2);
    r.y = (int)map_word((u32)v.y, slut2);
    r.z = (int)map_word((u32)v.z, slut2);
    r.w = (int)map_word((u32)v.w, slut2);
    return r;
}

// ---------------- K0: reset atomics ----------------
__global__ void k_reset() {
    if (threadIdx.x == 0) {
        g_maxx_bits = 0u; g_max_o1 = 0; g_max_o2 = 0; g_max_a3 = 0; g_max_aS = 0;
    }
}

// ---------------- K1: max|x| ----------------
__global__ __launch_bounds__(256) void k_maxx(const float* __restrict__ x) {
    __shared__ float sred[8];
    float mx = 0.f;
    const int n4 = (32 * CIN * HW) / 4;
    for (int i = blockIdx.x * blockDim.x + threadIdx.x; i < n4; i += gridDim.x * blockDim.x) {
        float4 v = ((const float4*)x)[i];
        mx = fmaxf(mx, fmaxf(fmaxf(fabsf(v.x), fabsf(v.y)), fmaxf(fabsf(v.z), fabsf(v.w))));
    }
    #pragma unroll
    for (int o = 16; o; o >>= 1) mx = fmaxf(mx, __shfl_xor_sync(0xffffffffu, mx, o));
    if ((threadIdx.x & 31) == 0) sred[threadIdx.x >> 5] = mx;
    __syncthreads();
    if (threadIdx.x == 0) {
        float m = sred[0];
        #pragma unroll
        for (int w = 1; w < 8; w++) m = fmaxf(m, sred[w]);
        atomicMax(&g_maxx_bits, __float_as_uint(m));
    }
}

// ---------------- K2: weight quant + BN folds + s_x ----------------
__global__ __launch_bounds__(256) void k_prep(
    const float* __restrict__ w1, const float* __restrict__ w2,
    const float* __restrict__ w3, const float* __restrict__ ws,
    const float* __restrict__ g1, const float* __restrict__ b1,
    const float* __restrict__ m1, const float* __restrict__ v1,
    const float* __restrict__ g2, const float* __restrict__ b2,
    const float* __restrict__ m2, const float* __restrict__ v2,
    const float* __restrict__ g3, const float* __restrict__ b3,
    const float* __restrict__ m3, const float* __restrict__ v3,
    const float* __restrict__ gs, const float* __restrict__ bs,
    const float* __restrict__ ms, const float* __restrict__ vs) {
    const int blk = blockIdx.x, t = threadIdx.x;
    if (blk < 4) {
        const float* w; int n; s8* dst;
        if (blk == 0)      { w = w1; n = PEXP * CIN;  dst = g_w1q; }
        else if (blk == 1) { w = w2; n = PEXP * 9;    dst = g_w2q; }
        else if (blk == 2) { w = w3; n = COUT * PEXP; dst = g_w3q; }
        else               { w = ws; n = COUT * CIN;  dst = g_wsq; }
        __shared__ float sred[256];
        __shared__ float s_si;
        float mx = 0.f;
        for (int i = t; i < n; i += 256) mx = fmaxf(mx, fabsf(w[i]));
        sred[t] = mx; __syncthreads();
        for (int s = 128; s > 0; s >>= 1) {
            if (t < s) sred[t] = fmaxf(sred[t], sred[t + s]);
            __syncthreads();
        }
        if (t == 0) {
            float m = fmaxf(sred[0], 1e-8f);
            float s = pow2ceil(__fdiv_rn(m, 7.0f));
            g_sw[blk] = s; s_si = 1.0f / s;
        }
        __syncthreads();
        float si = s_si;
        for (int i = t; i < n; i += 256) {
            float r = fminf(fmaxf(rintf(__fmul_rn(w[i], si)), -8.f), 7.f);
            if (blk == 1) { int p = i / 9, tap = i % 9; g_w2q[tap * PEXP + p] = (s8)(int)r; }
            else dst[i] = (s8)(int)r;
        }
    } else if (blk == 4) {
        for (int c = t; c < PEXP; c += 256) {
            float inv = __fmul_rn(g1[c], 1.0f / sqrtf(v1[c] + 1e-5f));
            g_inv1[c] = inv; g_add1[c] = __fsub_rn(b1[c], __fmul_rn(m1[c], inv));
        }
    } else if (blk == 5) {
        for (int c = t; c < PEXP; c += 256) {
            float inv = __fmul_rn(g2[c], 1.0f / sqrtf(v2[c] + 1e-5f));
            g_inv2[c] = inv; g_add2[c] = __fsub_rn(b2[c], __fmul_rn(m2[c], inv));
        }
    } else if (blk == 6) {
        for (int c = t; c < COUT; c += 256) {
            float inv = __fmul_rn(g3[c], 1.0f / sqrtf(v3[c] + 1e-5f));
            g_inv3[c] = inv; g_add3[c] = __fsub_rn(b3[c], __fmul_rn(m3[c], inv));
            float invs = __fmul_rn(gs[c], 1.0f / sqrtf(vs[c] + 1e-5f));
            g_invS[c] = invs; g_addS[c] = __fsub_rn(bs[c], __fmul_rn(ms[c], invs));
        }
    } else {
        if (t == 0) {
            float m = fmaxf(__uint_as_float(g_maxx_bits), 1e-8f);
            float s = pow2ceil(__fdiv_rn(m, 7.0f));
            g_sx = s; g_sxinv = 1.0f / s;
        }
    }
}

// ---------------- K3: quantize x, NCHW f32 -> NHWC int8 codes ----------------
__global__ __launch_bounds__(256) void k_qx(const float* __restrict__ x) {
    __shared__ s8 sm[64 * 68];
    const int b = blockIdx.x / 49;
    const int pix0 = (blockIdx.x % 49) * 64;          // within-image pixel base
    const int t = threadIdx.x;
    const float sxinv = g_sxinv;
    const int px = t & 63, cg = t >> 6;
    #pragma unroll
    for (int j = 0; j < 16; j++) {
        int c = cg * 16 + j;
        float v = x[(size_t)(b * CIN + c) * HW + pix0 + px];
        float q = fminf(fmaxf(rintf(__fmul_rn(v, sxinv)), -8.f), 7.f);
        sm[px * 68 + c] = (s8)(int)q;
    }
    __syncthreads();
    const int pix = t >> 2, cofs = (t & 3) * 16;
    const int* sp = (const int*)(sm + pix * 68 + cofs);
    int4 v = make_int4(sp[0], sp[1], sp[2], sp[3]);
    ((int4*)g_xq)[(size_t)(b * HW + pix0 + pix) * 4 + (t & 3)] = v;
}

// ---------------- K4: conv1 1x1 (64->384) + BN + relu4 ----------------
__global__ __launch_bounds__(256) void k_conv1() {
    __shared__ int4 xs4[128 * 5];      // 128 pix x 4 int4 (stride 5 -> 80B rows, conflict-free)
    __shared__ int4 ws4[64 * 5];
    __shared__ int s_wmax[8];
    const int pix0 = blockIdx.x * 128;
    const int p0   = blockIdx.y * 64;
    const int t = threadIdx.x;
    const int4* xg = (const int4*)g_xq;
    const int4* wg = (const int4*)g_w1q;
    #pragma unroll
    for (int i = t; i < 512; i += 256)
        xs4[(i >> 2) * 5 + (i & 3)] = xg[(size_t)(pix0 + (i >> 2)) * 4 + (i & 3)];
    if (t < 256) {
        int o = t >> 2, q = t & 3;
        ws4[o * 5 + q] = wg[(p0 + o) * 4 + q];
    }
    __syncthreads();
    int acc[8][4] = {};
    const int pi = t & 15, pj = t >> 4;
    #pragma unroll
    for (int k4 = 0; k4 < 4; k4++) {
        int4 A[8], B[4];
        #pragma unroll
        for (int i = 0; i < 8; i++) A[i] = xs4[(pi + 16 * i) * 5 + k4];
        #pragma unroll
        for (int j = 0; j < 4; j++) B[j] = ws4[(pj + 16 * j) * 5 + k4];
        #pragma unroll
        for (int i = 0; i < 8; i++)
            #pragma unroll
            for (int j = 0; j < 4; j++) {
                acc[i][j] = __dp4a(A[i].x, B[j].x, acc[i][j]);
                acc[i][j] = __dp4a(A[i].y, B[j].y, acc[i][j]);
                acc[i][j] = __dp4a(A[i].z, B[j].z, acc[i][j]);
                acc[i][j] = __dp4a(A[i].w, B[j].w, acc[i][j]);
            }
    }
    const float sc = __fmul_rn(g_sx, g_sw[0]);
    float inv[4], add[4];
    #pragma unroll
    for (int j = 0; j < 4; j++) { int p = p0 + pj + 16 * j; inv[j] = g_inv1[p]; add[j] = g_add1[p]; }
    __syncthreads();                       // xs4 reads done -> reuse as staging
    u8* so = (u8*)xs4;                     // 128*64 = 8192B <= 10240B
    int mymax = 0;
    #pragma unroll
    for (int i = 0; i < 8; i++)
        #pragma unroll
        for (int j = 0; j < 4; j++) {
            float raw = __fmul_rn(__int2float_rn(acc[i][j]), sc);
            float y = __fadd_rn(__fmul_rn(raw, inv[j]), add[j]);
            int code = clampi((int)rintf(__fmul_rn(y, 4.0f)), 0, 15);
            mymax = max(mymax, code);
            so[(pi + 16 * i) * 64 + (pj + 16 * j)] = (u8)code;
        }
    mymax = wredmax(mymax);
    if ((t & 31) == 0) s_wmax[t >> 5] = mymax;
    __syncthreads();
    const int4* s4 = (const int4*)so;
    #pragma unroll
    for (int i = t; i < 512; i += 256) {
        int pix = i >> 2, c16 = i & 3;
        ((int4*)g_o1)[(size_t)(pix0 + pix) * 24 + (p0 >> 4) + c16] = s4[i];
    }
    if (t == 0) {
        int m = s_wmax[0];
        #pragma unroll
        for (int w = 1; w < 8; w++) m = max(m, s_wmax[w]);
        atomicMax(&g_max_o1, m);
    }
}

// ---------------- K5: depthwise 3x3 + BN + relu4 (fused requant-map on load) ---
__global__ __launch_bounds__(384) void k_conv2() {
    __shared__ s8 sm[10 * 10 * PEXP];      // 38400 B
    __shared__ u32 slut2[256];
    __shared__ int s_wmax[12];
    const int b = blockIdx.x / 49;
    const int tile = blockIdx.x % 49;
    const int oy0 = (tile / 7) * 8, ox0 = (tile % 7) * 8;
    const int t = threadIdx.x;
    // inline requant LUT + scale (g_max_o1 final: conv1 grid completed)
    build_pairlut(slut2, t, g_max_o1);
    float s2p;
    {
        float m = fmaxf(__fmul_rn((float)g_max_o1, 0.25f), 1e-8f);
        float s = pow2ceil(__fdiv_rn(m, 7.0f));
        s2p = __fmul_rn(s, g_sw[1]);
    }
    __syncthreads();   // slut2 ready
    for (int idx = t; idx < 2400; idx += 384) {
        int cell = idx / 24, c16 = idx % 24;
        int iy = oy0 - 1 + cell / 10, ix = ox0 - 1 + cell % 10;
        int4 v = make_int4(0, 0, 0, 0);
        if (iy >= 0 && iy < 56 && ix >= 0 && ix < 56)
            v = map_int4(((const int4*)g_o1)[(size_t)(b * HW + iy * 56 + ix) * 24 + c16], slut2);
        ((int4*)sm)[cell * 24 + c16] = v;
    }
    __syncthreads();
    const int c4 = t % 96, strip = t / 96;
    int wl[9][4];                           // byte-isolated weights for dp4a
    #pragma unroll
    for (int tap = 0; tap < 9; tap++) {
        int w = ((const int*)g_w2q)[tap * 96 + c4];
        wl[tap][0] = w & 0x000000FF;
        wl[tap][1] = w & 0x0000FF00;
        wl[tap][2] = w & 0x00FF0000;
        wl[tap][3] = (int)((u32)w & 0xFF000000u);
    }
    float inv[4], add[4];
    #pragma unroll
    for (int l = 0; l < 4; l++) { int c = c4 * 4 + l; inv[l] = g_inv2[c]; add[l] = g_add2[c]; }
    int mymax = 0;
    #pragma unroll
    for (int sub = 0; sub < 4; sub++) {
        int base[4], oyv[4], oxv[4];
        #pragma unroll
        for (int k = 0; k < 4; k++) {
            int pix = strip * 16 + sub * 4 + k;
            int oy = pix >> 3, ox = pix & 7;
            oyv[k] = oy; oxv[k] = ox;
            base[k] = (oy * 10 + ox) * PEXP + c4 * 4;
        }
        int acc[4][4] = {};
        #pragma unroll
        for (int dy = 0; dy < 3; dy++)
            #pragma unroll
            for (int dx = 0; dx < 3; dx++) {
                int tap = dy * 3 + dx;
                int toff = (dy * 10 + dx) * PEXP;
                #pragma unroll
                for (int k = 0; k < 4; k++) {
                    int v = *(const int*)(sm + base[k] + toff);
                    acc[k][0] = __dp4a(v, wl[tap][0], acc[k][0]);
                    acc[k][1] = __dp4a(v, wl[tap][1], acc[k][1]);
                    acc[k][2] = __dp4a(v, wl[tap][2], acc[k][2]);
                    acc[k][3] = __dp4a(v, wl[tap][3], acc[k][3]);
                }
            }
        #pragma unroll
        for (int k = 0; k < 4; k++) {
            u32 pk = 0;
            #pragma unroll
            for (int l = 0; l < 4; l++) {
                float raw = __fmul_rn(__int2float_rn(acc[k][l]), s2p);
                float y = __fadd_rn(__fmul_rn(raw, inv[l]), add[l]);
                int code = clampi((int)rintf(__fmul_rn(y, 4.0f)), 0, 15);
                mymax = max(mymax, code);
                pk |= (u32)code << (8 * l);
            }
            *(u32*)(g_o2 + (size_t)(b * HW + (oy0 + oyv[k]) * 56 + (ox0 + oxv[k])) * PEXP + c4 * 4) = pk;
        }
    }
    mymax = wredmax(mymax);
    if ((t & 31) == 0) s_wmax[t >> 5] = mymax;
    __syncthreads();
    if (t == 0) {
        int m = s_wmax[0];
        #pragma unroll
        for (int w = 1; w < 12; w++) m = max(m, s_wmax[w]);
        atomicMax(&g_max_o2, m);
    }
}

// ---------------- K6: conv3 1x1 (384->96) -> int16 raw acc + |max| (fused map) --
__global__ __launch_bounds__(256) void k_conv3() {
    __shared__ int4 xs4[64 * 13];          // 64 pix x 12 int4 (stride 13 -> 208B rows)
    __shared__ int4 ws4[96 * 13];
    __shared__ short ss[96 * 64];
    __shared__ u32 slut2[256];
    __shared__ int s_wmax[8];
    const int pix0 = blockIdx.x * 64;
    const int t = threadIdx.x;
    build_pairlut(slut2, t, g_max_o2);     // g_max_o2 final: conv2 completed
    const int4* xg = (const int4*)g_o2;
    const int4* wg = (const int4*)g_w3q;
    const int pi = t & 15, pj = t >> 4;
    int acc[4][6] = {};
    for (int kc = 0; kc < 2; kc++) {
        __syncthreads();                   // slut2 ready (kc=0) / tile reads done (kc=1)
        for (int i = t; i < 768; i += 256) {
            int pix = i / 12, q = i % 12;
            int4 v = map_int4(xg[(size_t)(pix0 + pix) * 24 + kc * 12 + q], slut2);
            xs4[pix * 13 + q] = v;
        }
        for (int i = t; i < 1152; i += 256) {
            int o = i / 12, q = i % 12;
            ws4[o * 13 + q] = wg[o * 24 + kc * 12 + q];
        }
        __syncthreads();
        #pragma unroll
        for (int k4 = 0; k4 < 12; k4++) {
            int4 A[4], B[6];
            #pragma unroll
            for (int i = 0; i < 4; i++) A[i] = xs4[(pi + 16 * i) * 13 + k4];
            #pragma unroll
            for (int j = 0; j < 6; j++) B[j] = ws4[(pj + 16 * j) * 13 + k4];
            #pragma unroll
            for (int i = 0; i < 4; i++)
                #pragma unroll
                for (int j = 0; j < 6; j++) {
                    acc[i][j] = __dp4a(A[i].x, B[j].x, acc[i][j]);
                    acc[i][j] = __dp4a(A[i].y, B[j].y, acc[i][j]);
                    acc[i][j] = __dp4a(A[i].z, B[j].z, acc[i][j]);
                    acc[i][j] = __dp4a(A[i].w, B[j].w, acc[i][j]);
                }
        }
    }
    int amax = 0;
    #pragma unroll
    for (int i = 0; i < 4; i++)
        #pragma unroll
        for (int j = 0; j < 6; j++) {
            int a = acc[i][j];
            amax = max(amax, abs(a));
            ss[(pj + 16 * j) * 64 + (pi + 16 * i)] = (short)a;
        }
    amax = wredmax(amax);
    if ((t & 31) == 0) s_wmax[t >> 5] = amax;
    __syncthreads();
    const int bimg = pix0 / HW, hw0 = pix0 % HW;
    const int4* s4 = (const int4*)ss;
    #pragma unroll
    for (int i = t; i < 768; i += 256) {
        int o = i >> 3, seg = i & 7;
        ((int4*)g_acc3)[(size_t)(bimg * COUT + o) * 392 + (hw0 >> 3) + seg] = s4[i];
    }
    if (t == 0) {
        int m = s_wmax[0];
        #pragma unroll
        for (int w = 1; w < 8; w++) m = max(m, s_wmax[w]);
        atomicMax(&g_max_a3, m);
    }
}

// ---------------- K7: shortcut 1x1 (64->96) -> int16 raw acc + |max| ----------
__global__ __launch_bounds__(256) void k_convS() {
    __shared__ int4 xs4[64 * 5];
    __shared__ int4 ws4[96 * 5];
    __shared__ short ss[96 * 64];
    __shared__ int s_wmax[8];
    const int pix0 = blockIdx.x * 64;
    const int t = threadIdx.x;
    const int4* xg = (const int4*)g_xq;
    const int4* wg = (const int4*)g_wsq;
    if (t < 256) {
        int pix = t >> 2, q = t & 3;
        xs4[pix * 5 + q] = xg[(size_t)(pix0 + pix) * 4 + q];
    }
    #pragma unroll
    for (int i = t; i < 384; i += 256) {
        int o = i >> 2, q = i & 3;
        ws4[o * 5 + q] = wg[o * 4 + q];
    }
    __syncthreads();
    const int pi = t & 15, pj = t >> 4;
    int acc[4][6] = {};
    #pragma unroll
    for (int k4 = 0; k4 < 4; k4++) {
        int4 A[4], B[6];
        #pragma unroll
        for (int i = 0; i < 4; i++) A[i] = xs4[(pi + 16 * i) * 5 + k4];
        #pragma unroll
        for (int j = 0; j < 6; j++) B[j] = ws4[(pj + 16 * j) * 5 + k4];
        #pragma unroll
        for (int i = 0; i < 4; i++)
            #pragma unroll
            for (int j = 0; j < 6; j++) {
                acc[i][j] = __dp4a(A[i].x, B[j].x, acc[i][j]);
                acc[i][j] = __dp4a(A[i].y, B[j].y, acc[i][j]);
                acc[i][j] = __dp4a(A[i].z, B[j].z, acc[i][j]);
                acc[i][j] = __dp4a(A[i].w, B[j].w, acc[i][j]);
            }
    }
    int amax = 0;
    #pragma unroll
    for (int i = 0; i < 4; i++)
        #pragma unroll
        for (int j = 0; j < 6; j++) {
            int a = acc[i][j];
            amax = max(amax, abs(a));
            ss[(pj + 16 * j) * 64 + (pi + 16 * i)] = (short)a;
        }
    amax = wredmax(amax);
    if ((t & 31) == 0) s_wmax[t >> 5] = amax;
    __syncthreads();
    const int bimg = pix0 / HW, hw0 = pix0 % HW;
    const int4* s4 = (const int4*)ss;
    #pragma unroll
    for (int i = t; i < 768; i += 256) {
        int o = i >> 3, seg = i & 7;
        ((int4*)g_accS)[(size_t)(bimg * COUT + o) * 392 + (hw0 >> 3) + seg] = s4[i];
    }
    if (t == 0) {
        int m = s_wmax[0];
        #pragma unroll
        for (int w = 1; w < 8; w++) m = max(m, s_wmax[w]);
        atomicMax(&g_max_aS, m);
    }
}

// ---------------- K8: final requant scales ----------------
__global__ void k_scales() {
    if (threadIdx.x == 0) {
        float m2 = fmaxf(__fmul_rn((float)g_max_o2, 0.25f), 1e-8f);
        float s2 = pow2ceil(__fdiv_rn(m2, 7.0f));
        float s3prod = __fmul_rn(s2, g_sw[2]);
        float m3 = fmaxf(__fmul_rn(s3prod, (float)g_max_a3), 1e-8f);
        float sO = pow2ceil(__fdiv_rn(m3, 127.0f));
        g_r3 = __fdiv_rn(s3prod, sO); g_sO = sO;       // exact pow2 ratio
        float sxw = __fmul_rn(g_sx, g_sw[3]);
        float mS = fmaxf(__fmul_rn(sxw, (float)g_max_aS), 1e-8f);
        float sS = pow2ceil(__fdiv_rn(mS, 7.0f));
        g_rS = __fdiv_rn(sxw, sS); g_sS = sS;
    }
}

// ---------------- K9: fused epilogue -> output (NCHW f32) ----------------
__global__ __launch_bounds__(256) void k_epi(float* __restrict__ out) {
    const float r3 = g_r3, sO = g_sO, rS = g_rS, sS = g_sS;
    const int n8 = (32 * COUT * HW) / 8;   // 1204224
    for (int i = blockIdx.x * blockDim.x + threadIdx.x; i < n8; i += gridDim.x * blockDim.x) {
        int c = (i / 392) % COUT;
        float inv3 = g_inv3[c], add3 = g_add3[c], invS = g_invS[c], addS = g_addS[c];
        int4 av = ((const int4*)g_acc3)[i];
        int4 sv = ((const int4*)g_accS)[i];
        const short* ap = (const short*)&av;
        const short* sp = (const short*)&sv;
        float r[8];
        #pragma unroll
        for (int l = 0; l < 8; l++) {
            float q3 = fminf(fmaxf(rintf(__fmul_rn((float)ap[l], r3)), -128.f), 127.f);
            float y3 = __fadd_rn(__fmul_rn(__fmul_rn(q3, sO), inv3), add3);
            float qS = fminf(fmaxf(rintf(__fmul_rn((float)sp[l], rS)), -8.f), 7.f);
            float yS = __fadd_rn(__fmul_rn(__fmul_rn(qS, sS), invS), addS);
            float sum = __fadd_rn(y3, yS);
            float code = fminf(fmaxf(rintf(__fmul_rn(sum, 4.0f)), 0.f), 15.f);
            r[l] = __fmul_rn(code, 0.25f);
        }
        float4* o4 = (float4*)out;
        o4[(size_t)i * 2]     = make_float4(r[0], r[1], r[2], r[3]);
        o4[(size_t)i * 2 + 1] = make_float4(r[4], r[5], r[6], r[7]);
    }
}

// ---------------- launch ----------------
extern "C" void kernel_launch(void* const* d_in, const int* in_sizes, int n_in,
                              void* d_out, int out_size) {
    const float* x  = (const float*)d_in[0];
    const float* w1 = (const float*)d_in[1];
    const float* g1 = (const float*)d_in[2];
    const float* b1 = (const float*)d_in[3];
    const float* m1 = (const float*)d_in[4];
    const float* v1 = (const float*)d_in[5];
    const float* w2 = (const float*)d_in[6];
    const float* g2 = (const float*)d_in[7];
    const float* b2 = (const float*)d_in[8];
    const float* m2 = (const float*)d_in[9];
    const float* v2 = (const float*)d_in[10];
    const float* w3 = (const float*)d_in[11];
    const float* g3 = (const float*)d_in[12];
    const float* b3 = (const float*)d_in[13];
    const float* m3 = (const float*)d_in[14];
    const float* v3 = (const float*)d_in[15];
    const float* ws = (const float*)d_in[16];
    const float* gs = (const float*)d_in[17];
    const float* bs = (const float*)d_in[18];
    const float* ms = (const float*)d_in[19];
    const float* vs = (const float*)d_in[20];

    k_reset<<<1, 32>>>();
    k_maxx<<<512, 256>>>(x);
    k_prep<<<8, 256>>>(w1, w2, w3, ws, g1, b1, m1, v1, g2, b2, m2, v2,
                       g3, b3, m3, v3, gs, bs, ms, vs);
    k_qx<<<1568, 256>>>(x);
    k_conv1<<<dim3(784, 6), 256>>>();
    k_conv2<<<1568, 384>>>();
    k_conv3<<<1568, 256>>>();
    k_convS<<<1568, 256>>>();
    k_scales<<<1, 32>>>();
    k_epi<<<4704, 256>>>((float*)d_out);
}

// round 15
// speedup vs baseline: 1.9353x; 1.2478x over previous
#include <cuda_runtime.h>
#include <cstdint>

typedef unsigned int u32;
typedef unsigned short u16;
typedef signed char  s8;
typedef unsigned char u8;

#define HW    3136            // 56*56
#define NPIX  100352          // 32*3136
#define CIN   64
#define PEXP  384
#define COUT  96

// ---------------- device scratch ----------------
static __device__ __align__(16) s8    g_xq [(size_t)NPIX * CIN];     // x int4 codes, NHWC
static __device__ __align__(16) u8    g_o1 [(size_t)NPIX * PEXP];    // stage1 relu4 codes 0..15
static __device__ __align__(16) u8    g_o2 [(size_t)NPIX * PEXP];    // stage2 relu4 codes 0..15
static __device__ __align__(16) short g_acc3[(size_t)32 * COUT * HW]; // conv3 raw int acc, NCHW
static __device__ __align__(16) short g_accS[(size_t)32 * COUT * HW]; // shortcut raw int acc, NCHW
static __device__ __align__(16) s8    g_w1q[PEXP * CIN];
static __device__ __align__(16) s8    g_w2q[9 * PEXP];               // [tap][384]
static __device__ __align__(16) s8    g_w3q[COUT * PEXP];
static __device__ __align__(16) s8    g_wsq[COUT * CIN];
static __device__ float g_inv1[PEXP], g_add1[PEXP], g_inv2[PEXP], g_add2[PEXP];
static __device__ float g_inv3[COUT], g_add3[COUT], g_invS[COUT], g_addS[COUT];
static __device__ u32   g_maxx_bits;
static __device__ int   g_max_o1, g_max_o2, g_max_a3, g_max_aS;
static __device__ float g_sx, g_sxinv;
static __device__ float g_sw[4];                 // s_w1, s_w2, s_w3, s_ws
static __device__ float g_r3, g_sO, g_rS, g_sS;  // final requant factors

// ---------------- helpers ----------------
__device__ __forceinline__ float pow2ceil(float q) {
    // exact exp2(ceil(log2(q))), q > 0
    int e; float f = frexpf(q, &e);     // q = f * 2^e, f in [0.5, 1)
    if (f == 0.5f) e -= 1;
    return ldexpf(1.0f, e);
}
__device__ __forceinline__ int clampi(int v, int lo, int hi) {
    return min(max(v, lo), hi);
}
__device__ __forceinline__ int wredmax(int v) {
    #pragma unroll
    for (int o = 16; o; o >>= 1) v = max(v, __shfl_xor_sync(0xffffffffu, v, o));
    return v;
}

// int8 tensor-core MMA: D(16x8,s32) += A(16x32,s8 row) * B(32x8,s8 col)
__device__ __forceinline__ void mma_s8(int& c0, int& c1, int& c2, int& c3,
                                       int a0, int a1, int a2, int a3,
                                       int b0, int b1) {
    asm volatile(
        "mma.sync.aligned.m16n8k32.row.col.s32.s8.s8.s32 "
        "{%0,%1,%2,%3},{%4,%5,%6,%7},{%8,%9},{%0,%1,%2,%3};"
        : "+r"(c0), "+r"(c1), "+r"(c2), "+r"(c3)
        : "r"(a0), "r"(a1), "r"(a2), "r"(a3), "r"(b0), "r"(b1));
}

// Build 256-entry byte-pair requant LUT in shared from a max-code value.
// Entry [c1*16+c0] = mapped(c0) | mapped(c1)<<8 ; mapped(c) in 0..7 (never negative).
__device__ __forceinline__ void build_pairlut(u32* slut2, int t, int maxcode) {
    float m = fmaxf(__fmul_rn((float)maxcode, 0.25f), 1e-8f);
    float s = pow2ceil(__fdiv_rn(m, 7.0f));
    float si = 1.0f / s;
    if (t < 256) {
        int c0 = t & 15, c1 = t >> 4;
        int v0 = (int)fminf(fmaxf(rintf(__fmul_rn(__fmul_rn((float)c0, 0.25f), si)), -8.f), 7.f);
        int v1 = (int)fminf(fmaxf(rintf(__fmul_rn(__fmul_rn((float)c1, 0.25f), si)), -8.f), 7.f);
        slut2[t] = (u32)(v0 | (v1 << 8));
    }
}
__device__ __forceinline__ u32 map_word(u32 w, const u32* slut2) {
    u32 i0 = (w & 15u) | ((w >> 4) & 0xF0u);
    u32 i1 = ((w >> 16) & 15u) | ((w >> 20) & 0xF0u);
    return slut2[i0] | (slut2[i1] << 16);
}
__device__ __forceinline__ int4 map_int4(int4 v, const u32* slut2) {
    int4 r;
    r.x = (int)map_word((u32)v.x, slut2);
    r.y = (int)map_word((u32)v.y, slut2);
    r.z = (int)map_word((u32)v.z, slut2);
    r.w = (int)map_word((u32)v.w, slut2);
    return r;
}

// ---------------- K0: reset atomics ----------------
__global__ void k_reset() {
    if (threadIdx.x == 0) {
        g_maxx_bits = 0u; g_max_o1 = 0; g_max_o2 = 0; g_max_a3 = 0; g_max_aS = 0;
    }
}

// ---------------- K1: max|x| ----------------
__global__ __launch_bounds__(256) void k_maxx(const float* __restrict__ x) {
    __shared__ float sred[8];
    float mx = 0.f;
    const int n4 = (32 * CIN * HW) / 4;
    for (int i = blockIdx.x * blockDim.x + threadIdx.x; i < n4; i += gridDim.x * blockDim.x) {
        float4 v = ((const float4*)x)[i];
        mx = fmaxf(mx, fmaxf(fmaxf(fabsf(v.x), fabsf(v.y)), fmaxf(fabsf(v.z), fabsf(v.w))));
    }
    #pragma unroll
    for (int o = 16; o; o >>= 1) mx = fmaxf(mx, __shfl_xor_sync(0xffffffffu, mx, o));
    if ((threadIdx.x & 31) == 0) sred[threadIdx.x >> 5] = mx;
    __syncthreads();
    if (threadIdx.x == 0) {
        float m = sred[0];
        #pragma unroll
        for (int w = 1; w < 8; w++) m = fmaxf(m, sred[w]);
        atomicMax(&g_maxx_bits, __float_as_uint(m));
    }
}

// ---------------- K2: weight quant + BN folds + s_x ----------------
__global__ __launch_bounds__(256) void k_prep(
    const float* __restrict__ w1, const float* __restrict__ w2,
    const float* __restrict__ w3, const float* __restrict__ ws,
    const float* __restrict__ g1, const float* __restrict__ b1,
    const float* __restrict__ m1, const float* __restrict__ v1,
    const float* __restrict__ g2, const float* __restrict__ b2,
    const float* __restrict__ m2, const float* __restrict__ v2,
    const float* __restrict__ g3, const float* __restrict__ b3,
    const float* __restrict__ m3, const float* __restrict__ v3,
    const float* __restrict__ gs, const float* __restrict__ bs,
    const float* __restrict__ ms, const float* __restrict__ vs) {
    const int blk = blockIdx.x, t = threadIdx.x;
    if (blk < 4) {
        const float* w; int n; s8* dst;
        if (blk == 0)      { w = w1; n = PEXP * CIN;  dst = g_w1q; }
        else if (blk == 1) { w = w2; n = PEXP * 9;    dst = g_w2q; }
        else if (blk == 2) { w = w3; n = COUT * PEXP; dst = g_w3q; }
        else               { w = ws; n = COUT * CIN;  dst = g_wsq; }
        __shared__ float sred[256];
        __shared__ float s_si;
        float mx = 0.f;
        for (int i = t; i < n; i += 256) mx = fmaxf(mx, fabsf(w[i]));
        sred[t] = mx; __syncthreads();
        for (int s = 128; s > 0; s >>= 1) {
            if (t < s) sred[t] = fmaxf(sred[t], sred[t + s]);
            __syncthreads();
        }
        if (t == 0) {
            float m = fmaxf(sred[0], 1e-8f);
            float s = pow2ceil(__fdiv_rn(m, 7.0f));
            g_sw[blk] = s; s_si = 1.0f / s;
        }
        __syncthreads();
        float si = s_si;
        for (int i = t; i < n; i += 256) {
            float r = fminf(fmaxf(rintf(__fmul_rn(w[i], si)), -8.f), 7.f);
            if (blk == 1) { int p = i / 9, tap = i % 9; g_w2q[tap * PEXP + p] = (s8)(int)r; }
            else dst[i] = (s8)(int)r;
        }
    } else if (blk == 4) {
        for (int c = t; c < PEXP; c += 256) {
            float inv = __fmul_rn(g1[c], 1.0f / sqrtf(v1[c] + 1e-5f));
            g_inv1[c] = inv; g_add1[c] = __fsub_rn(b1[c], __fmul_rn(m1[c], inv));
        }
    } else if (blk == 5) {
        for (int c = t; c < PEXP; c += 256) {
            float inv = __fmul_rn(g2[c], 1.0f / sqrtf(v2[c] + 1e-5f));
            g_inv2[c] = inv; g_add2[c] = __fsub_rn(b2[c], __fmul_rn(m2[c], inv));
        }
    } else if (blk == 6) {
        for (int c = t; c < COUT; c += 256) {
            float inv = __fmul_rn(g3[c], 1.0f / sqrtf(v3[c] + 1e-5f));
            g_inv3[c] = inv; g_add3[c] = __fsub_rn(b3[c], __fmul_rn(m3[c], inv));
            float invs = __fmul_rn(gs[c], 1.0f / sqrtf(vs[c] + 1e-5f));
            g_invS[c] = invs; g_addS[c] = __fsub_rn(bs[c], __fmul_rn(ms[c], invs));
        }
    } else {
        if (t == 0) {
            float m = fmaxf(__uint_as_float(g_maxx_bits), 1e-8f);
            float s = pow2ceil(__fdiv_rn(m, 7.0f));
            g_sx = s; g_sxinv = 1.0f / s;
        }
    }
}

// ---------------- K3: quantize x, NCHW f32 -> NHWC int8 codes ----------------
__global__ __launch_bounds__(256) void k_qx(const float* __restrict__ x) {
    __shared__ s8 sm[64 * 68];
    const int b = blockIdx.x / 49;
    const int pix0 = (blockIdx.x % 49) * 64;          // within-image pixel base
    const int t = threadIdx.x;
    const float sxinv = g_sxinv;
    const int px = t & 63, cg = t >> 6;
    #pragma unroll
    for (int j = 0; j < 16; j++) {
        int c = cg * 16 + j;
        float v = x[(size_t)(b * CIN + c) * HW + pix0 + px];
        float q = fminf(fmaxf(rintf(__fmul_rn(v, sxinv)), -8.f), 7.f);
        sm[px * 68 + c] = (s8)(int)q;
    }
    __syncthreads();
    const int pix = t >> 2, cofs = (t & 3) * 16;
    const int* sp = (const int*)(sm + pix * 68 + cofs);
    int4 v = make_int4(sp[0], sp[1], sp[2], sp[3]);
    ((int4*)g_xq)[(size_t)(b * HW + pix0 + pix) * 4 + (t & 3)] = v;
}

// ---------------- K4: conv1 1x1 (64->384) via mma.s8 + BN + relu4 ------------
// Block: 128 pixels x 128 outs. Grid (784, 3).
__global__ __launch_bounds__(256) void k_conv1() {
    __shared__ s8 As[128 * 80];        // 128 pix x 64 k, rows padded to 80B (bank-clean)
    __shared__ s8 Bs[128 * 80];        // 128 out x 64 k
    __shared__ u8 so[128 * 144];       // code staging, rows padded to 144B
    __shared__ float sInv[128], sAdd[128];
    __shared__ int s_wmax[8];
    const int pix0 = blockIdx.x * 128;
    const int p0   = blockIdx.y * 128;
    const int t = threadIdx.x;
    const int4* xg = (const int4*)g_xq;
    const int4* wg = (const int4*)g_w1q;
    #pragma unroll
    for (int i = t; i < 512; i += 256) {
        int pix = i >> 2, q = i & 3;
        *(int4*)(As + pix * 80 + q * 16) = xg[(size_t)(pix0 + pix) * 4 + q];
    }
    #pragma unroll
    for (int i = t; i < 512; i += 256) {
        int o = i >> 2, q = i & 3;
        *(int4*)(Bs + o * 80 + q * 16) = wg[(p0 + o) * 4 + q];
    }
    if (t < 128) { sInv[t] = g_inv1[p0 + t]; sAdd[t] = g_add1[p0 + t]; }
    __syncthreads();
    const int w = t >> 5, l = t & 31, g = l >> 2, t4 = l & 3;
    const int wp0 = w * 16;
    int a[2][4];
    #pragma unroll
    for (int ki = 0; ki < 2; ki++) {
        a[ki][0] = *(const int*)(As + (wp0 + g) * 80 + ki * 32 + 4 * t4);
        a[ki][1] = *(const int*)(As + (wp0 + g + 8) * 80 + ki * 32 + 4 * t4);
        a[ki][2] = *(const int*)(As + (wp0 + g) * 80 + ki * 32 + 16 + 4 * t4);
        a[ki][3] = *(const int*)(As + (wp0 + g + 8) * 80 + ki * 32 + 16 + 4 * t4);
    }
    int c[16][4];
    #pragma unroll
    for (int nf = 0; nf < 16; nf++) { c[nf][0] = c[nf][1] = c[nf][2] = c[nf][3] = 0; }
    #pragma unroll
    for (int ki = 0; ki < 2; ki++)
        #pragma unroll
        for (int nf = 0; nf < 16; nf++) {
            int b0 = *(const int*)(Bs + (nf * 8 + g) * 80 + ki * 32 + 4 * t4);
            int b1 = *(const int*)(Bs + (nf * 8 + g) * 80 + ki * 32 + 16 + 4 * t4);
            mma_s8(c[nf][0], c[nf][1], c[nf][2], c[nf][3],
                   a[ki][0], a[ki][1], a[ki][2], a[ki][3], b0, b1);
        }
    const float sc = __fmul_rn(g_sx, g_sw[0]);
    int mymax = 0;
    #pragma unroll
    for (int nf = 0; nf < 16; nf++) {
        int ob = nf * 8 + 2 * t4;
        float inv0 = sInv[ob], add0 = sAdd[ob];
        float inv1 = sInv[ob + 1], add1 = sAdd[ob + 1];
        #pragma unroll
        for (int i = 0; i < 2; i++) {
            int pix = wp0 + g + 8 * i;
            float r0 = __fmul_rn(__int2float_rn(c[nf][2 * i]), sc);
            float y0 = __fadd_rn(__fmul_rn(r0, inv0), add0);
            int q0 = clampi((int)rintf(__fmul_rn(y0, 4.0f)), 0, 15);
            float r1 = __fmul_rn(__int2float_rn(c[nf][2 * i + 1]), sc);
            float y1 = __fadd_rn(__fmul_rn(r1, inv1), add1);
            int q1 = clampi((int)rintf(__fmul_rn(y1, 4.0f)), 0, 15);
            mymax = max(mymax, max(q0, q1));
            *(u16*)(so + pix * 144 + ob) = (u16)(q0 | (q1 << 8));
        }
    }
    mymax = wredmax(mymax);
    if (l == 0) s_wmax[w] = mymax;
    __syncthreads();
    #pragma unroll
    for (int i = t; i < 1024; i += 256) {
        int pix = i >> 3, c16 = i & 7;
        ((int4*)g_o1)[(size_t)(pix0 + pix) * 24 + (p0 >> 4) + c16] =
            *(const int4*)(so + pix * 144 + c16 * 16);
    }
    if (t == 0) {
        int m = s_wmax[0];
        #pragma unroll
        for (int ww = 1; ww < 8; ww++) m = max(m, s_wmax[ww]);
        atomicMax(&g_max_o1, m);
    }
}

// ---------------- K5: depthwise 3x3 + BN + relu4 (fused requant-map on load) ---
__global__ __launch_bounds__(384) void k_conv2() {
    __shared__ s8 sm[10 * 10 * PEXP];      // 38400 B
    __shared__ u32 slut2[256];
    __shared__ int s_wmax[12];
    const int b = blockIdx.x / 49;
    const int tile = blockIdx.x % 49;
    const int oy0 = (tile / 7) * 8, ox0 = (tile % 7) * 8;
    const int t = threadIdx.x;
    build_pairlut(slut2, t, g_max_o1);
    float s2p;
    {
        float m = fmaxf(__fmul_rn((float)g_max_o1, 0.25f), 1e-8f);
        float s = pow2ceil(__fdiv_rn(m, 7.0f));
        s2p = __fmul_rn(s, g_sw[1]);
    }
    __syncthreads();   // slut2 ready
    for (int idx = t; idx < 2400; idx += 384) {
        int cell = idx / 24, c16 = idx % 24;
        int iy = oy0 - 1 + cell / 10, ix = ox0 - 1 + cell % 10;
        int4 v = make_int4(0, 0, 0, 0);
        if (iy >= 0 && iy < 56 && ix >= 0 && ix < 56)
            v = map_int4(((const int4*)g_o1)[(size_t)(b * HW + iy * 56 + ix) * 24 + c16], slut2);
        ((int4*)sm)[cell * 24 + c16] = v;
    }
    __syncthreads();
    const int c4 = t % 96, strip = t / 96;
    int wl[9][4];                           // byte-isolated weights for dp4a
    #pragma unroll
    for (int tap = 0; tap < 9; tap++) {
        int w = ((const int*)g_w2q)[tap * 96 + c4];
        wl[tap][0] = w & 0x000000FF;
        wl[tap][1] = w & 0x0000FF00;
        wl[tap][2] = w & 0x00FF0000;
        wl[tap][3] = (int)((u32)w & 0xFF000000u);
    }
    float inv[4], add[4];
    #pragma unroll
    for (int l = 0; l < 4; l++) { int c = c4 * 4 + l; inv[l] = g_inv2[c]; add[l] = g_add2[c]; }
    int mymax = 0;
    #pragma unroll
    for (int sub = 0; sub < 4; sub++) {
        int base[4], oyv[4], oxv[4];
        #pragma unroll
        for (int k = 0; k < 4; k++) {
            int pix = strip * 16 + sub * 4 + k;
            int oy = pix >> 3, ox = pix & 7;
            oyv[k] = oy; oxv[k] = ox;
            base[k] = (oy * 10 + ox) * PEXP + c4 * 4;
        }
        int acc[4][4] = {};
        #pragma unroll
        for (int dy = 0; dy < 3; dy++)
            #pragma unroll
            for (int dx = 0; dx < 3; dx++) {
                int tap = dy * 3 + dx;
                int toff = (dy * 10 + dx) * PEXP;
                #pragma unroll
                for (int k = 0; k < 4; k++) {
                    int v = *(const int*)(sm + base[k] + toff);
                    acc[k][0] = __dp4a(v, wl[tap][0], acc[k][0]);
                    acc[k][1] = __dp4a(v, wl[tap][1], acc[k][1]);
                    acc[k][2] = __dp4a(v, wl[tap][2], acc[k][2]);
                    acc[k][3] = __dp4a(v, wl[tap][3], acc[k][3]);
                }
            }
        #pragma unroll
        for (int k = 0; k < 4; k++) {
            u32 pk = 0;
            #pragma unroll
            for (int l = 0; l < 4; l++) {
                float raw = __fmul_rn(__int2float_rn(acc[k][l]), s2p);
                float y = __fadd_rn(__fmul_rn(raw, inv[l]), add[l]);
                int code = clampi((int)rintf(__fmul_rn(y, 4.0f)), 0, 15);
                mymax = max(mymax, code);
                pk |= (u32)code << (8 * l);
            }
            *(u32*)(g_o2 + (size_t)(b * HW + (oy0 + oyv[k]) * 56 + (ox0 + oxv[k])) * PEXP + c4 * 4) = pk;
        }
    }
    mymax = wredmax(mymax);
    if ((t & 31) == 0) s_wmax[t >> 5] = mymax;
    __syncthreads();
    if (t == 0) {
        int m = s_wmax[0];
        #pragma unroll
        for (int w = 1; w < 12; w++) m = max(m, s_wmax[w]);
        atomicMax(&g_max_o2, m);
    }
}

// ---------------- K6: conv3 1x1 (384->96) via mma.s8 -> int16 acc + |max| ------
// Block: 64 pixels x 96 outs, K=384. Dynamic smem (rows padded to 400B).
#define C3_AS    0
#define C3_BS    25600
#define C3_SS    64000
#define C3_LUT   76288
#define C3_WMAX  77312
#define C3_SMEM  77344
__global__ __launch_bounds__(256) void k_conv3() {
    extern __shared__ char dsm[];
    s8*   As    = (s8*)(dsm + C3_AS);      // 64 x 400
    s8*   Bs    = (s8*)(dsm + C3_BS);      // 96 x 400
    short* ss   = (short*)(dsm + C3_SS);   // 96 x 64
    u32*  slut2 = (u32*)(dsm + C3_LUT);
    int*  s_wmax = (int*)(dsm + C3_WMAX);
    const int pix0 = blockIdx.x * 64;
    const int t = threadIdx.x;
    build_pairlut(slut2, t, g_max_o2);     // g_max_o2 final (conv2 done)
    __syncthreads();
    const int4* xg = (const int4*)g_o2;
    const int4* wg = (const int4*)g_w3q;
    for (int i = t; i < 1536; i += 256) {
        int pix = i / 24, q = i % 24;
        *(int4*)(As + pix * 400 + q * 16) = map_int4(xg[(size_t)(pix0 + pix) * 24 + q], slut2);
    }
    for (int i = t; i < 2304; i += 256) {
        int o = i / 24, q = i % 24;
        *(int4*)(Bs + o * 400 + q * 16) = wg[o * 24 + q];
    }
    __syncthreads();
    const int w = t >> 5, l = t & 31, g = l >> 2, t4 = l & 3;
    const int pg = w >> 1, oh = w & 1;
    const int prow = pg * 16, obase = oh * 48;
    int c[6][4];
    #pragma unroll
    for (int nf = 0; nf < 6; nf++) { c[nf][0] = c[nf][1] = c[nf][2] = c[nf][3] = 0; }
    #pragma unroll
    for (int ki = 0; ki < 12; ki++) {
        int a0 = *(const int*)(As + (prow + g) * 400 + ki * 32 + 4 * t4);
        int a1 = *(const int*)(As + (prow + g + 8) * 400 + ki * 32 + 4 * t4);
        int a2 = *(const int*)(As + (prow + g) * 400 + ki * 32 + 16 + 4 * t4);
        int a3 = *(const int*)(As + (prow + g + 8) * 400 + ki * 32 + 16 + 4 * t4);
        #pragma unroll
        for (int nf = 0; nf < 6; nf++) {
            int b0 = *(const int*)(Bs + (obase + nf * 8 + g) * 400 + ki * 32 + 4 * t4);
            int b1 = *(const int*)(Bs + (obase + nf * 8 + g) * 400 + ki * 32 + 16 + 4 * t4);
            mma_s8(c[nf][0], c[nf][1], c[nf][2], c[nf][3], a0, a1, a2, a3, b0, b1);
        }
    }
    int amax = 0;
    #pragma unroll
    for (int nf = 0; nf < 6; nf++)
        #pragma unroll
        for (int i = 0; i < 2; i++)
            #pragma unroll
            for (int j = 0; j < 2; j++) {
                int a = c[nf][2 * i + j];
                amax = max(amax, abs(a));
                ss[(obase + nf * 8 + 2 * t4 + j) * 64 + (prow + g + 8 * i)] = (short)a;
            }
    amax = wredmax(amax);
    if (l == 0) s_wmax[w] = amax;
    __syncthreads();
    const int bimg = pix0 / HW, hw0 = pix0 % HW;
    const int4* s4 = (const int4*)ss;
    #pragma unroll
    for (int i = t; i < 768; i += 256) {
        int o = i >> 3, seg = i & 7;
        ((int4*)g_acc3)[(size_t)(bimg * COUT + o) * 392 + (hw0 >> 3) + seg] = s4[i];
    }
    if (t == 0) {
        int m = s_wmax[0];
        #pragma unroll
        for (int ww = 1; ww < 8; ww++) m = max(m, s_wmax[ww]);
        atomicMax(&g_max_a3, m);
    }
}

// ---------------- K7: shortcut 1x1 (64->96) via mma.s8 -> int16 acc + |max| ----
__global__ __launch_bounds__(256) void k_convS() {
    __shared__ s8 As[64 * 80];
    __shared__ s8 Bs[96 * 80];
    __shared__ short ss[96 * 64];
    __shared__ int s_wmax[8];
    const int pix0 = blockIdx.x * 64;
    const int t = threadIdx.x;
    const int4* xg = (const int4*)g_xq;
    const int4* wg = (const int4*)g_wsq;
    if (t < 256) {
        int pix = t >> 2, q = t & 3;
        *(int4*)(As + pix * 80 + q * 16) = xg[(size_t)(pix0 + pix) * 4 + q];
    }
    #pragma unroll
    for (int i = t; i < 384; i += 256) {
        int o = i >> 2, q = i & 3;
        *(int4*)(Bs + o * 80 + q * 16) = wg[o * 4 + q];
    }
    __syncthreads();
    const int w = t >> 5, l = t & 31, g = l >> 2, t4 = l & 3;
    const int pg = w >> 1, oh = w & 1;
    const int prow = pg * 16, obase = oh * 48;
    int a[2][4];
    #pragma unroll
    for (int ki = 0; ki < 2; ki++) {
        a[ki][0] = *(const int*)(As + (prow + g) * 80 + ki * 32 + 4 * t4);
        a[ki][1] = *(const int*)(As + (prow + g + 8) * 80 + ki * 32 + 4 * t4);
        a[ki][2] = *(const int*)(As + (prow + g) * 80 + ki * 32 + 16 + 4 * t4);
        a[ki][3] = *(const int*)(As + (prow + g + 8) * 80 + ki * 32 + 16 + 4 * t4);
    }
    int c[6][4];
    #pragma unroll
    for (int nf = 0; nf < 6; nf++) { c[nf][0] = c[nf][1] = c[nf][2] = c[nf][3] = 0; }
    #pragma unroll
    for (int ki = 0; ki < 2; ki++)
        #pragma unroll
        for (int nf = 0; nf < 6; nf++) {
            int b0 = *(const int*)(Bs + (obase + nf * 8 + g) * 80 + ki * 32 + 4 * t4);
            int b1 = *(const int*)(Bs + (obase + nf * 8 + g) * 80 + ki * 32 + 16 + 4 * t4);
            mma_s8(c[nf][0], c[nf][1], c[nf][2], c[nf][3],
                   a[ki][0], a[ki][1], a[ki][2], a[ki][3], b0, b1);
        }
    int amax = 0;
    #pragma unroll
    for (int nf = 0; nf < 6; nf++)
        #pragma unroll
        for (int i = 0; i < 2; i++)
            #pragma unroll
            for (int j = 0; j < 2; j++) {
                int a0 = c[nf][2 * i + j];
                amax = max(amax, abs(a0));
                ss[(obase + nf * 8 + 2 * t4 + j) * 64 + (prow + g + 8 * i)] = (short)a0;
            }
    amax = wredmax(amax);
    if (l == 0) s_wmax[w] = amax;
    __syncthreads();
    const int bimg = pix0 / HW, hw0 = pix0 % HW;
    const int4* s4 = (const int4*)ss;
    #pragma unroll
    for (int i = t; i < 768; i += 256) {
        int o = i >> 3, seg = i & 7;
        ((int4*)g_accS)[(size_t)(bimg * COUT + o) * 392 + (hw0 >> 3) + seg] = s4[i];
    }
    if (t == 0) {
        int m = s_wmax[0];
        #pragma unroll
        for (int ww = 1; ww < 8; ww++) m = max(m, s_wmax[ww]);
        atomicMax(&g_max_aS, m);
    }
}

// ---------------- K8: final requant scales ----------------
__global__ void k_scales() {
    if (threadIdx.x == 0) {
        float m2 = fmaxf(__fmul_rn((float)g_max_o2, 0.25f), 1e-8f);
        float s2 = pow2ceil(__fdiv_rn(m2, 7.0f));
        float s3prod = __fmul_rn(s2, g_sw[2]);
        float m3 = fmaxf(__fmul_rn(s3prod, (float)g_max_a3), 1e-8f);
        float sO = pow2ceil(__fdiv_rn(m3, 127.0f));
        g_r3 = __fdiv_rn(s3prod, sO); g_sO = sO;       // exact pow2 ratio
        float sxw = __fmul_rn(g_sx, g_sw[3]);
        float mS = fmaxf(__fmul_rn(sxw, (float)g_max_aS), 1e-8f);
        float sS = pow2ceil(__fdiv_rn(mS, 7.0f));
        g_rS = __fdiv_rn(sxw, sS); g_sS = sS;
    }
}

// ---------------- K9: fused epilogue -> output (NCHW f32) ----------------
__global__ __launch_bounds__(256) void k_epi(float* __restrict__ out) {
    const float r3 = g_r3, sO = g_sO, rS = g_rS, sS = g_sS;
    const int n8 = (32 * COUT * HW) / 8;   // 1204224
    for (int i = blockIdx.x * blockDim.x + threadIdx.x; i < n8; i += gridDim.x * blockDim.x) {
        int c = (i / 392) % COUT;
        float inv3 = g_inv3[c], add3 = g_add3[c], invS = g_invS[c], addS = g_addS[c];
        int4 av = ((const int4*)g_acc3)[i];
        int4 sv = ((const int4*)g_accS)[i];
        const short* ap = (const short*)&av;
        const short* sp = (const short*)&sv;
        float r[8];
        #pragma unroll
        for (int l = 0; l < 8; l++) {
            float q3 = fminf(fmaxf(rintf(__fmul_rn((float)ap[l], r3)), -128.f), 127.f);
            float y3 = __fadd_rn(__fmul_rn(__fmul_rn(q3, sO), inv3), add3);
            float qS = fminf(fmaxf(rintf(__fmul_rn((float)sp[l], rS)), -8.f), 7.f);
            float yS = __fadd_rn(__fmul_rn(__fmul_rn(qS, sS), invS), addS);
            float sum = __fadd_rn(y3, yS);
            float code = fminf(fmaxf(rintf(__fmul_rn(sum, 4.0f)), 0.f), 15.f);
            r[l] = __fmul_rn(code, 0.25f);
        }
        float4* o4 = (float4*)out;
        o4[(size_t)i * 2]     = make_float4(r[0], r[1], r[2], r[3]);
        o4[(size_t)i * 2 + 1] = make_float4(r[4], r[5], r[6], r[7]);
    }
}

// ---------------- launch ----------------
extern "C" void kernel_launch(void* const* d_in, const int* in_sizes, int n_in,
                              void* d_out, int out_size) {
    const float* x  = (const float*)d_in[0];
    const float* w1 = (const float*)d_in[1];
    const float* g1 = (const float*)d_in[2];
    const float* b1 = (const float*)d_in[3];
    const float* m1 = (const float*)d_in[4];
    const float* v1 = (const float*)d_in[5];
    const float* w2 = (const float*)d_in[6];
    const float* g2 = (const float*)d_in[7];
    const float* b2 = (const float*)d_in[8];
    const float* m2 = (const float*)d_in[9];
    const float* v2 = (const float*)d_in[10];
    const float* w3 = (const float*)d_in[11];
    const float* g3 = (const float*)d_in[12];
    const float* b3 = (const float*)d_in[13];
    const float* m3 = (const float*)d_in[14];
    const float* v3 = (const float*)d_in[15];
    const float* ws = (const float*)d_in[16];
    const float* gs = (const float*)d_in[17];
    const float* bs = (const float*)d_in[18];
    const float* ms = (const float*)d_in[19];
    const float* vs = (const float*)d_in[20];

    cudaFuncSetAttribute(k_conv3, cudaFuncAttributeMaxDynamicSharedMemorySize, C3_SMEM);

    k_reset<<<1, 32>>>();
    k_maxx<<<512, 256>>>(x);
    k_prep<<<8, 256>>>(w1, w2, w3, ws, g1, b1, m1, v1, g2, b2, m2, v2,
                       g3, b3, m3, v3, gs, bs, ms, vs);
    k_qx<<<1568, 256>>>(x);
    k_conv1<<<dim3(784, 3), 256>>>();
    k_conv2<<<1568, 384>>>();
    k_conv3<<<1568, 256, C3_SMEM>>>();
    k_convS<<<1568, 256>>>();
    k_scales<<<1, 32>>>();
    k_epi<<<4704, 256>>>((float*)d_out);
}

// round 16
// speedup vs baseline: 2.0618x; 1.0654x over previous
#include <cuda_runtime.h>
#include <cstdint>

typedef unsigned int u32;
typedef unsigned short u16;
typedef signed char  s8;
typedef unsigned char u8;

#define HW    3136            // 56*56
#define NPIX  100352          // 32*3136
#define CIN   64
#define PEXP  384
#define COUT  96

// ---------------- device scratch ----------------
static __device__ __align__(16) s8    g_xq [(size_t)NPIX * CIN];      // x int4 codes, NHWC (s8)
static __device__ __align__(16) u8    g_o1 [(size_t)NPIX * (PEXP/2)]; // stage1 codes, 2/byte
static __device__ __align__(16) u8    g_o2 [(size_t)NPIX * (PEXP/2)]; // stage2 codes, 2/byte
static __device__ __align__(16) short g_acc3[(size_t)32 * COUT * HW]; // conv3 raw int acc, NCHW
static __device__ __align__(16) short g_accS[(size_t)32 * COUT * HW]; // shortcut raw int acc, NCHW
static __device__ __align__(16) s8    g_w1q[PEXP * CIN];
static __device__ __align__(16) s8    g_w2q[9 * PEXP];                // [tap][384]
static __device__ __align__(16) s8    g_w3q[COUT * PEXP];
static __device__ __align__(16) s8    g_wsq[COUT * CIN];
static __device__ float g_inv1[PEXP], g_add1[PEXP], g_inv2[PEXP], g_add2[PEXP];
static __device__ float g_inv3[COUT], g_add3[COUT], g_invS[COUT], g_addS[COUT];
static __device__ u32   g_maxx_bits;
static __device__ int   g_max_o1, g_max_o2, g_max_a3, g_max_aS;
static __device__ float g_sx, g_sxinv;
static __device__ float g_sw[4];                 // s_w1, s_w2, s_w3, s_ws

// ---------------- helpers ----------------
__device__ __forceinline__ float pow2ceil(float q) {
    // exact exp2(ceil(log2(q))), q > 0
    int e; float f = frexpf(q, &e);     // q = f * 2^e, f in [0.5, 1)
    if (f == 0.5f) e -= 1;
    return ldexpf(1.0f, e);
}
__device__ __forceinline__ int clampi(int v, int lo, int hi) {
    return min(max(v, lo), hi);
}
__device__ __forceinline__ int wredmax(int v) {
    #pragma unroll
    for (int o = 16; o; o >>= 1) v = max(v, __shfl_xor_sync(0xffffffffu, v, o));
    return v;
}

// int8 tensor-core MMA: D(16x8,s32) += A(16x32,s8 row) * B(32x8,s8 col)
__device__ __forceinline__ void mma_s8(int& c0, int& c1, int& c2, int& c3,
                                       int a0, int a1, int a2, int a3,
                                       int b0, int b1) {
    asm volatile(
        "mma.sync.aligned.m16n8k32.row.col.s32.s8.s8.s32 "
        "{%0,%1,%2,%3},{%4,%5,%6,%7},{%8,%9},{%0,%1,%2,%3};"
        : "+r"(c0), "+r"(c1), "+r"(c2), "+r"(c3)
        : "r"(a0), "r"(a1), "r"(a2), "r"(a3), "r"(b0), "r"(b1));
}

// 256-entry requant LUT: index = packed byte (lo nibble = even channel code,
// hi nibble = odd channel code); value = mapped(lo) | mapped(hi)<<8 (both 0..7).
__device__ __forceinline__ void build_pairlut(u32* slut2, int t, int maxcode) {
    float m = fmaxf(__fmul_rn((float)maxcode, 0.25f), 1e-8f);
    float s = pow2ceil(__fdiv_rn(m, 7.0f));
    float si = 1.0f / s;
    if (t < 256) {
        int c0 = t & 15, c1 = t >> 4;
        int v0 = (int)fminf(fmaxf(rintf(__fmul_rn(__fmul_rn((float)c0, 0.25f), si)), -8.f), 7.f);
        int v1 = (int)fminf(fmaxf(rintf(__fmul_rn(__fmul_rn((float)c1, 0.25f), si)), -8.f), 7.f);
        slut2[t] = (u32)(v0 | (v1 << 8));
    }
}
// Unpack+map one packed word (8 codes) -> two unpacked s8 words (8 mapped values)
__device__ __forceinline__ void unmap_word(u32 w, const u32* slut2, u32& lo, u32& hi) {
    lo = slut2[w & 255u] | (slut2[(w >> 8) & 255u] << 16);
    hi = slut2[(w >> 16) & 255u] | (slut2[w >> 24] << 16);
}
__device__ __forceinline__ void unmap_int4(int4 v, const u32* slut2, int4& o0, int4& o1) {
    u32 a, b;
    unmap_word((u32)v.x, slut2, a, b); o0.x = (int)a; o0.y = (int)b;
    unmap_word((u32)v.y, slut2, a, b); o0.z = (int)a; o0.w = (int)b;
    unmap_word((u32)v.z, slut2, a, b); o1.x = (int)a; o1.y = (int)b;
    unmap_word((u32)v.w, slut2, a, b); o1.z = (int)a; o1.w = (int)b;
}

// ---------------- K0: reset atomics ----------------
__global__ void k_reset() {
    if (threadIdx.x == 0) {
        g_maxx_bits = 0u; g_max_o1 = 0; g_max_o2 = 0; g_max_a3 = 0; g_max_aS = 0;
    }
}

// ---------------- K1: max|x| ----------------
__global__ __launch_bounds__(256) void k_maxx(const float* __restrict__ x) {
    __shared__ float sred[8];
    float mx = 0.f;
    const int n4 = (32 * CIN * HW) / 4;
    for (int i = blockIdx.x * blockDim.x + threadIdx.x; i < n4; i += gridDim.x * blockDim.x) {
        float4 v = ((const float4*)x)[i];
        mx = fmaxf(mx, fmaxf(fmaxf(fabsf(v.x), fabsf(v.y)), fmaxf(fabsf(v.z), fabsf(v.w))));
    }
    #pragma unroll
    for (int o = 16; o; o >>= 1) mx = fmaxf(mx, __shfl_xor_sync(0xffffffffu, mx, o));
    if ((threadIdx.x & 31) == 0) sred[threadIdx.x >> 5] = mx;
    __syncthreads();
    if (threadIdx.x == 0) {
        float m = sred[0];
        #pragma unroll
        for (int w = 1; w < 8; w++) m = fmaxf(m, sred[w]);
        atomicMax(&g_maxx_bits, __float_as_uint(m));
    }
}

// ---------------- K2: weight quant + BN folds + s_x ----------------
__global__ __launch_bounds__(256) void k_prep(
    const float* __restrict__ w1, const float* __restrict__ w2,
    const float* __restrict__ w3, const float* __restrict__ ws,
    const float* __restrict__ g1, const float* __restrict__ b1,
    const float* __restrict__ m1, const float* __restrict__ v1,
    const float* __restrict__ g2, const float* __restrict__ b2,
    const float* __restrict__ m2, const float* __restrict__ v2,
    const float* __restrict__ g3, const float* __restrict__ b3,
    const float* __restrict__ m3, const float* __restrict__ v3,
    const float* __restrict__ gs, const float* __restrict__ bs,
    const float* __restrict__ ms, const float* __restrict__ vs) {
    const int blk = blockIdx.x, t = threadIdx.x;
    if (blk < 4) {
        const float* w; int n; s8* dst;
        if (blk == 0)      { w = w1; n = PEXP * CIN;  dst = g_w1q; }
        else if (blk == 1) { w = w2; n = PEXP * 9;    dst = g_w2q; }
        else if (blk == 2) { w = w3; n = COUT * PEXP; dst = g_w3q; }
        else               { w = ws; n = COUT * CIN;  dst = g_wsq; }
        __shared__ float sred[256];
        __shared__ float s_si;
        float mx = 0.f;
        for (int i = t; i < n; i += 256) mx = fmaxf(mx, fabsf(w[i]));
        sred[t] = mx; __syncthreads();
        for (int s = 128; s > 0; s >>= 1) {
            if (t < s) sred[t] = fmaxf(sred[t], sred[t + s]);
            __syncthreads();
        }
        if (t == 0) {
            float m = fmaxf(sred[0], 1e-8f);
            float s = pow2ceil(__fdiv_rn(m, 7.0f));
            g_sw[blk] = s; s_si = 1.0f / s;
        }
        __syncthreads();
        float si = s_si;
        for (int i = t; i < n; i += 256) {
            float r = fminf(fmaxf(rintf(__fmul_rn(w[i], si)), -8.f), 7.f);
            if (blk == 1) { int p = i / 9, tap = i % 9; g_w2q[tap * PEXP + p] = (s8)(int)r; }
            else dst[i] = (s8)(int)r;
        }
    } else if (blk == 4) {
        for (int c = t; c < PEXP; c += 256) {
            float inv = __fmul_rn(g1[c], 1.0f / sqrtf(v1[c] + 1e-5f));
            g_inv1[c] = inv; g_add1[c] = __fsub_rn(b1[c], __fmul_rn(m1[c], inv));
        }
    } else if (blk == 5) {
        for (int c = t; c < PEXP; c += 256) {
            float inv = __fmul_rn(g2[c], 1.0f / sqrtf(v2[c] + 1e-5f));
            g_inv2[c] = inv; g_add2[c] = __fsub_rn(b2[c], __fmul_rn(m2[c], inv));
        }
    } else if (blk == 6) {
        for (int c = t; c < COUT; c += 256) {
            float inv = __fmul_rn(g3[c], 1.0f / sqrtf(v3[c] + 1e-5f));
            g_inv3[c] = inv; g_add3[c] = __fsub_rn(b3[c], __fmul_rn(m3[c], inv));
            float invs = __fmul_rn(gs[c], 1.0f / sqrtf(vs[c] + 1e-5f));
            g_invS[c] = invs; g_addS[c] = __fsub_rn(bs[c], __fmul_rn(ms[c], invs));
        }
    } else {
        if (t == 0) {
            float m = fmaxf(__uint_as_float(g_maxx_bits), 1e-8f);
            float s = pow2ceil(__fdiv_rn(m, 7.0f));
            g_sx = s; g_sxinv = 1.0f / s;
        }
    }
}

// ---------------- K3: quantize x, NCHW f32 -> NHWC int8 codes ----------------
__global__ __launch_bounds__(256) void k_qx(const float* __restrict__ x) {
    __shared__ s8 sm[64 * 68];
    const int b = blockIdx.x / 49;
    const int pix0 = (blockIdx.x % 49) * 64;          // within-image pixel base
    const int t = threadIdx.x;
    const float sxinv = g_sxinv;
    const int px = t & 63, cg = t >> 6;
    #pragma unroll
    for (int j = 0; j < 16; j++) {
        int c = cg * 16 + j;
        float v = x[(size_t)(b * CIN + c) * HW + pix0 + px];
        float q = fminf(fmaxf(rintf(__fmul_rn(v, sxinv)), -8.f), 7.f);
        sm[px * 68 + c] = (s8)(int)q;
    }
    __syncthreads();
    const int pix = t >> 2, cofs = (t & 3) * 16;
    const int* sp = (const int*)(sm + pix * 68 + cofs);
    int4 v = make_int4(sp[0], sp[1], sp[2], sp[3]);
    ((int4*)g_xq)[(size_t)(b * HW + pix0 + pix) * 4 + (t & 3)] = v;
}

// ---------------- K4: conv1 1x1 (64->384) via mma.s8 + BN + relu4 ------------
// Block: 128 pixels x 128 outs. Grid (784, 3). Packed nibble output.
__global__ __launch_bounds__(256) void k_conv1() {
    __shared__ s8 As[128 * 80];        // 128 pix x 64 k, rows padded to 80B
    __shared__ s8 Bs[128 * 80];        // 128 out x 64 k
    __shared__ u8 so[128 * 112];       // packed staging: 64 bytes/pixel, rows padded to 112B
    __shared__ float sInv[128], sAdd[128];
    __shared__ int s_wmax[8];
    const int pix0 = blockIdx.x * 128;
    const int p0   = blockIdx.y * 128;
    const int t = threadIdx.x;
    const int4* xg = (const int4*)g_xq;
    const int4* wg = (const int4*)g_w1q;
    #pragma unroll
    for (int i = t; i < 512; i += 256) {
        int pix = i >> 2, q = i & 3;
        *(int4*)(As + pix * 80 + q * 16) = xg[(size_t)(pix0 + pix) * 4 + q];
    }
    #pragma unroll
    for (int i = t; i < 512; i += 256) {
        int o = i >> 2, q = i & 3;
        *(int4*)(Bs + o * 80 + q * 16) = wg[(p0 + o) * 4 + q];
    }
    if (t < 128) { sInv[t] = g_inv1[p0 + t]; sAdd[t] = g_add1[p0 + t]; }
    __syncthreads();
    const int w = t >> 5, l = t & 31, g = l >> 2, t4 = l & 3;
    const int wp0 = w * 16;
    int a[2][4];
    #pragma unroll
    for (int ki = 0; ki < 2; ki++) {
        a[ki][0] = *(const int*)(As + (wp0 + g) * 80 + ki * 32 + 4 * t4);
        a[ki][1] = *(const int*)(As + (wp0 + g + 8) * 80 + ki * 32 + 4 * t4);
        a[ki][2] = *(const int*)(As + (wp0 + g) * 80 + ki * 32 + 16 + 4 * t4);
        a[ki][3] = *(const int*)(As + (wp0 + g + 8) * 80 + ki * 32 + 16 + 4 * t4);
    }
    int c[16][4];
    #pragma unroll
    for (int nf = 0; nf < 16; nf++) { c[nf][0] = c[nf][1] = c[nf][2] = c[nf][3] = 0; }
    #pragma unroll
    for (int ki = 0; ki < 2; ki++)
        #pragma unroll
        for (int nf = 0; nf < 16; nf++) {
            int b0 = *(const int*)(Bs + (nf * 8 + g) * 80 + ki * 32 + 4 * t4);
            int b1 = *(const int*)(Bs + (nf * 8 + g) * 80 + ki * 32 + 16 + 4 * t4);
            mma_s8(c[nf][0], c[nf][1], c[nf][2], c[nf][3],
                   a[ki][0], a[ki][1], a[ki][2], a[ki][3], b0, b1);
        }
    const float sc = __fmul_rn(g_sx, g_sw[0]);
    int mymax = 0;
    #pragma unroll
    for (int nf = 0; nf < 16; nf++) {
        int ob = nf * 8 + 2 * t4;          // even channel of the pair
        float inv0 = sInv[ob], add0 = sAdd[ob];
        float inv1 = sInv[ob + 1], add1 = sAdd[ob + 1];
        #pragma unroll
        for (int i = 0; i < 2; i++) {
            int pix = wp0 + g + 8 * i;
            float r0 = __fmul_rn(__int2float_rn(c[nf][2 * i]), sc);
            float y0 = __fadd_rn(__fmul_rn(r0, inv0), add0);
            int q0 = clampi((int)rintf(__fmul_rn(y0, 4.0f)), 0, 15);
            float r1 = __fmul_rn(__int2float_rn(c[nf][2 * i + 1]), sc);
            float y1 = __fadd_rn(__fmul_rn(r1, inv1), add1);
            int q1 = clampi((int)rintf(__fmul_rn(y1, 4.0f)), 0, 15);
            mymax = max(mymax, max(q0, q1));
            so[pix * 112 + (ob >> 1)] = (u8)(q0 | (q1 << 4));   // lo nibble = even ch
        }
    }
    mymax = wredmax(mymax);
    if (l == 0) s_wmax[w] = mymax;
    __syncthreads();
    // copy packed staging (64B/pixel) to global (192B/pixel rows, offset p0/2)
    #pragma unroll
    for (int i = t; i < 512; i += 256) {
        int pix = i >> 2, c16 = i & 3;
        ((int4*)g_o1)[(size_t)(pix0 + pix) * 12 + (p0 >> 5) + c16] =
            *(const int4*)(so + pix * 112 + c16 * 16);
    }
    if (t == 0) {
        int m = s_wmax[0];
        #pragma unroll
        for (int ww = 1; ww < 8; ww++) m = max(m, s_wmax[ww]);
        atomicMax(&g_max_o1, m);
    }
}

// ---------------- K5: depthwise 3x3 + BN + relu4 (packed in/out, map on load) --
__global__ __launch_bounds__(384) void k_conv2() {
    __shared__ s8 sm[10 * 10 * PEXP];      // 38400 B (unpacked mapped s8)
    __shared__ u32 slut2[256];
    __shared__ int s_wmax[12];
    const int b = blockIdx.x / 49;
    const int tile = blockIdx.x % 49;
    const int oy0 = (tile / 7) * 8, ox0 = (tile % 7) * 8;
    const int t = threadIdx.x;
    build_pairlut(slut2, t, g_max_o1);
    float s2p;
    {
        float m = fmaxf(__fmul_rn((float)g_max_o1, 0.25f), 1e-8f);
        float s = pow2ceil(__fdiv_rn(m, 7.0f));
        s2p = __fmul_rn(s, g_sw[1]);
    }
    __syncthreads();   // slut2 ready
    for (int idx = t; idx < 1200; idx += 384) {
        int cell = idx / 12, q = idx % 12;
        int iy = oy0 - 1 + cell / 10, ix = ox0 - 1 + cell % 10;
        int4 o0 = make_int4(0, 0, 0, 0), o1 = make_int4(0, 0, 0, 0);
        if (iy >= 0 && iy < 56 && ix >= 0 && ix < 56) {
            int4 v = ((const int4*)g_o1)[(size_t)(b * HW + iy * 56 + ix) * 12 + q];
            unmap_int4(v, slut2, o0, o1);
        }
        ((int4*)sm)[cell * 24 + q * 2]     = o0;
        ((int4*)sm)[cell * 24 + q * 2 + 1] = o1;
    }
    __syncthreads();
    const int c4 = t % 96, strip = t / 96;
    int wl[9][4];                           // byte-isolated weights for dp4a
    #pragma unroll
    for (int tap = 0; tap < 9; tap++) {
        int w = ((const int*)g_w2q)[tap * 96 + c4];
        wl[tap][0] = w & 0x000000FF;
        wl[tap][1] = w & 0x0000FF00;
        wl[tap][2] = w & 0x00FF0000;
        wl[tap][3] = (int)((u32)w & 0xFF000000u);
    }
    float inv[4], add[4];
    #pragma unroll
    for (int l = 0; l < 4; l++) { int c = c4 * 4 + l; inv[l] = g_inv2[c]; add[l] = g_add2[c]; }
    int mymax = 0;
    #pragma unroll
    for (int sub = 0; sub < 4; sub++) {
        int base[4], oyv[4], oxv[4];
        #pragma unroll
        for (int k = 0; k < 4; k++) {
            int pix = strip * 16 + sub * 4 + k;
            int oy = pix >> 3, ox = pix & 7;
            oyv[k] = oy; oxv[k] = ox;
            base[k] = (oy * 10 + ox) * PEXP + c4 * 4;
        }
        int acc[4][4] = {};
        #pragma unroll
        for (int dy = 0; dy < 3; dy++)
            #pragma unroll
            for (int dx = 0; dx < 3; dx++) {
                int tap = dy * 3 + dx;
                int toff = (dy * 10 + dx) * PEXP;
                #pragma unroll
                for (int k = 0; k < 4; k++) {
                    int v = *(const int*)(sm + base[k] + toff);
                    acc[k][0] = __dp4a(v, wl[tap][0], acc[k][0]);
                    acc[k][1] = __dp4a(v, wl[tap][1], acc[k][1]);
                    acc[k][2] = __dp4a(v, wl[tap][2], acc[k][2]);
                    acc[k][3] = __dp4a(v, wl[tap][3], acc[k][3]);
                }
            }
        #pragma unroll
        for (int k = 0; k < 4; k++) {
            u32 pk = 0;
            #pragma unroll
            for (int l = 0; l < 4; l++) {
                float raw = __fmul_rn(__int2float_rn(acc[k][l]), s2p);
                float y = __fadd_rn(__fmul_rn(raw, inv[l]), add[l]);
                int code = clampi((int)rintf(__fmul_rn(y, 4.0f)), 0, 15);
                mymax = max(mymax, code);
                pk |= (u32)code << (4 * l);           // pack 4 codes into 2 bytes
            }
            *(u16*)(g_o2 + (size_t)(b * HW + (oy0 + oyv[k]) * 56 + (ox0 + oxv[k])) * (PEXP/2) + c4 * 2) = (u16)pk;
        }
    }
    mymax = wredmax(mymax);
    if ((t & 31) == 0) s_wmax[t >> 5] = mymax;
    __syncthreads();
    if (t == 0) {
        int m = s_wmax[0];
        #pragma unroll
        for (int w = 1; w < 12; w++) m = max(m, s_wmax[w]);
        atomicMax(&g_max_o2, m);
    }
}

// ---------------- K6: conv3 1x1 (384->96) via mma.s8 -> int16 acc + |max| ------
// Block: 64 pixels x 96 outs, K=384. Dynamic smem (rows padded to 400B).
#define C3_AS    0
#define C3_BS    25600
#define C3_SS    64000
#define C3_LUT   76288
#define C3_WMAX  77312
#define C3_SMEM  77344
__global__ __launch_bounds__(256) void k_conv3() {
    extern __shared__ char dsm[];
    s8*   As    = (s8*)(dsm + C3_AS);      // 64 x 400
    s8*   Bs    = (s8*)(dsm + C3_BS);      // 96 x 400
    short* ss   = (short*)(dsm + C3_SS);   // 96 x 64
    u32*  slut2 = (u32*)(dsm + C3_LUT);
    int*  s_wmax = (int*)(dsm + C3_WMAX);
    const int pix0 = blockIdx.x * 64;
    const int t = threadIdx.x;
    build_pairlut(slut2, t, g_max_o2);     // g_max_o2 final (conv2 done)
    __syncthreads();
    const int4* xg = (const int4*)g_o2;
    const int4* wg = (const int4*)g_w3q;
    for (int i = t; i < 768; i += 256) {
        int pix = i / 12, q = i % 12;
        int4 o0, o1;
        unmap_int4(xg[(size_t)(pix0 + pix) * 12 + q], slut2, o0, o1);
        *(int4*)(As + pix * 400 + q * 32)      = o0;
        *(int4*)(As + pix * 400 + q * 32 + 16) = o1;
    }
    for (int i = t; i < 2304; i += 256) {
        int o = i / 24, q = i % 24;
        *(int4*)(Bs + o * 400 + q * 16) = wg[o * 24 + q];
    }
    __syncthreads();
    const int w = t >> 5, l = t & 31, g = l >> 2, t4 = l & 3;
    const int pg = w >> 1, oh = w & 1;
    const int prow = pg * 16, obase = oh * 48;
    int c[6][4];
    #pragma unroll
    for (int nf = 0; nf < 6; nf++) { c[nf][0] = c[nf][1] = c[nf][2] = c[nf][3] = 0; }
    #pragma unroll
    for (int ki = 0; ki < 12; ki++) {
        int a0 = *(const int*)(As + (prow + g) * 400 + ki * 32 + 4 * t4);
        int a1 = *(const int*)(As + (prow + g + 8) * 400 + ki * 32 + 4 * t4);
        int a2 = *(const int*)(As + (prow + g) * 400 + ki * 32 + 16 + 4 * t4);
        int a3 = *(const int*)(As + (prow + g + 8) * 400 + ki * 32 + 16 + 4 * t4);
        #pragma unroll
        for (int nf = 0; nf < 6; nf++) {
            int b0 = *(const int*)(Bs + (obase + nf * 8 + g) * 400 + ki * 32 + 4 * t4);
            int b1 = *(const int*)(Bs + (obase + nf * 8 + g) * 400 + ki * 32 + 16 + 4 * t4);
            mma_s8(c[nf][0], c[nf][1], c[nf][2], c[nf][3], a0, a1, a2, a3, b0, b1);
        }
    }
    int amax = 0;
    #pragma unroll
    for (int nf = 0; nf < 6; nf++)
        #pragma unroll
        for (int i = 0; i < 2; i++)
            #pragma unroll
            for (int j = 0; j < 2; j++) {
                int a = c[nf][2 * i + j];
                amax = max(amax, abs(a));
                ss[(obase + nf * 8 + 2 * t4 + j) * 64 + (prow + g + 8 * i)] = (short)a;
            }
    amax = wredmax(amax);
    if (l == 0) s_wmax[w] = amax;
    __syncthreads();
    const int bimg = pix0 / HW, hw0 = pix0 % HW;
    const int4* s4 = (const int4*)ss;
    #pragma unroll
    for (int i = t; i < 768; i += 256) {
        int o = i >> 3, seg = i & 7;
        ((int4*)g_acc3)[(size_t)(bimg * COUT + o) * 392 + (hw0 >> 3) + seg] = s4[i];
    }
    if (t == 0) {
        int m = s_wmax[0];
        #pragma unroll
        for (int ww = 1; ww < 8; ww++) m = max(m, s_wmax[ww]);
        atomicMax(&g_max_a3, m);
    }
}

// ---------------- K7: shortcut 1x1 (64->96) via mma.s8 -> int16 acc + |max| ----
__global__ __launch_bounds__(256) void k_convS() {
    __shared__ s8 As[64 * 80];
    __shared__ s8 Bs[96 * 80];
    __shared__ short ss[96 * 64];
    __shared__ int s_wmax[8];
    const int pix0 = blockIdx.x * 64;
    const int t = threadIdx.x;
    const int4* xg = (const int4*)g_xq;
    const int4* wg = (const int4*)g_wsq;
    if (t < 256) {
        int pix = t >> 2, q = t & 3;
        *(int4*)(As + pix * 80 + q * 16) = xg[(size_t)(pix0 + pix) * 4 + q];
    }
    #pragma unroll
    for (int i = t; i < 384; i += 256) {
        int o = i >> 2, q = i & 3;
        *(int4*)(Bs + o * 80 + q * 16) = wg[o * 4 + q];
    }
    __syncthreads();
    const int w = t >> 5, l = t & 31, g = l >> 2, t4 = l & 3;
    const int pg = w >> 1, oh = w & 1;
    const int prow = pg * 16, obase = oh * 48;
    int a[2][4];
    #pragma unroll
    for (int ki = 0; ki < 2; ki++) {
        a[ki][0] = *(const int*)(As + (prow + g) * 80 + ki * 32 + 4 * t4);
        a[ki][1] = *(const int*)(As + (prow + g + 8) * 80 + ki * 32 + 4 * t4);
        a[ki][2] = *(const int*)(As + (prow + g) * 80 + ki * 32 + 16 + 4 * t4);
        a[ki][3] = *(const int*)(As + (prow + g + 8) * 80 + ki * 32 + 16 + 4 * t4);
    }
    int c[6][4];
    #pragma unroll
    for (int nf = 0; nf < 6; nf++) { c[nf][0] = c[nf][1] = c[nf][2] = c[nf][3] = 0; }
    #pragma unroll
    for (int ki = 0; ki < 2; ki++)
        #pragma unroll
        for (int nf = 0; nf < 6; nf++) {
            int b0 = *(const int*)(Bs + (obase + nf * 8 + g) * 80 + ki * 32 + 4 * t4);
            int b1 = *(const int*)(Bs + (obase + nf * 8 + g) * 80 + ki * 32 + 16 + 4 * t4);
            mma_s8(c[nf][0], c[nf][1], c[nf][2], c[nf][3],
                   a[ki][0], a[ki][1], a[ki][2], a[ki][3], b0, b1);
        }
    int amax = 0;
    #pragma unroll
    for (int nf = 0; nf < 6; nf++)
        #pragma unroll
        for (int i = 0; i < 2; i++)
            #pragma unroll
            for (int j = 0; j < 2; j++) {
                int a0 = c[nf][2 * i + j];
                amax = max(amax, abs(a0));
                ss[(obase + nf * 8 + 2 * t4 + j) * 64 + (prow + g + 8 * i)] = (short)a0;
            }
    amax = wredmax(amax);
    if (l == 0) s_wmax[w] = amax;
    __syncthreads();
    const int bimg = pix0 / HW, hw0 = pix0 % HW;
    const int4* s4 = (const int4*)ss;
    #pragma unroll
    for (int i = t; i < 768; i += 256) {
        int o = i >> 3, seg = i & 7;
        ((int4*)g_accS)[(size_t)(bimg * COUT + o) * 392 + (hw0 >> 3) + seg] = s4[i];
    }
    if (t == 0) {
        int m = s_wmax[0];
        #pragma unroll
        for (int ww = 1; ww < 8; ww++) m = max(m, s_wmax[ww]);
        atomicMax(&g_max_aS, m);
    }
}

// ---------------- K8: fused epilogue (scales computed inline) -> output --------
__global__ __launch_bounds__(256) void k_epi(float* __restrict__ out) {
    // same float ops as the old k_scales, recomputed uniformly per thread
    float m2 = fmaxf(__fmul_rn((float)g_max_o2, 0.25f), 1e-8f);
    float s2 = pow2ceil(__fdiv_rn(m2, 7.0f));
    float s3prod = __fmul_rn(s2, g_sw[2]);
    float m3 = fmaxf(__fmul_rn(s3prod, (float)g_max_a3), 1e-8f);
    float sO = pow2ceil(__fdiv_rn(m3, 127.0f));
    float r3 = __fdiv_rn(s3prod, sO);
    float sxw = __fmul_rn(g_sx, g_sw[3]);
    float mS = fmaxf(__fmul_rn(sxw, (float)g_max_aS), 1e-8f);
    float sS = pow2ceil(__fdiv_rn(mS, 7.0f));
    float rS = __fdiv_rn(sxw, sS);
    const int n8 = (32 * COUT * HW) / 8;   // 1204224
    for (int i = blockIdx.x * blockDim.x + threadIdx.x; i < n8; i += gridDim.x * blockDim.x) {
        int c = (i / 392) % COUT;
        float inv3 = g_inv3[c], add3 = g_add3[c], invS = g_invS[c], addS = g_addS[c];
        int4 av = ((const int4*)g_acc3)[i];
        int4 sv = ((const int4*)g_accS)[i];
        const short* ap = (const short*)&av;
        const short* sp = (const short*)&sv;
        float r[8];
        #pragma unroll
        for (int l = 0; l < 8; l++) {
            float q3 = fminf(fmaxf(rintf(__fmul_rn((float)ap[l], r3)), -128.f), 127.f);
            float y3 = __fadd_rn(__fmul_rn(__fmul_rn(q3, sO), inv3), add3);
            float qS = fminf(fmaxf(rintf(__fmul_rn((float)sp[l], rS)), -8.f), 7.f);
            float yS = __fadd_rn(__fmul_rn(__fmul_rn(qS, sS), invS), addS);
            float sum = __fadd_rn(y3, yS);
            float code = fminf(fmaxf(rintf(__fmul_rn(sum, 4.0f)), 0.f), 15.f);
            r[l] = __fmul_rn(code, 0.25f);
        }
        float4* o4 = (float4*)out;
        o4[(size_t)i * 2]     = make_float4(r[0], r[1], r[2], r[3]);
        o4[(size_t)i * 2 + 1] = make_float4(r[4], r[5], r[6], r[7]);
    }
}

// ---------------- launch ----------------
extern "C" void kernel_launch(void* const* d_in, const int* in_sizes, int n_in,
                              void* d_out, int out_size) {
    const float* x  = (const float*)d_in[0];
    const float* w1 = (const float*)d_in[1];
    const float* g1 = (const float*)d_in[2];
    const float* b1 = (const float*)d_in[3];
    const float* m1 = (const float*)d_in[4];
    const float* v1 = (const float*)d_in[5];
    const float* w2 = (const float*)d_in[6];
    const float* g2 = (const float*)d_in[7];
    const float* b2 = (const float*)d_in[8];
    const float* m2 = (const float*)d_in[9];
    const float* v2 = (const float*)d_in[10];
    const float* w3 = (const float*)d_in[11];
    const float* g3 = (const float*)d_in[12];
    const float* b3 = (const float*)d_in[13];
    const float* m3 = (const float*)d_in[14];
    const float* v3 = (const float*)d_in[15];
    const float* ws = (const float*)d_in[16];
    const float* gs = (const float*)d_in[17];
    const float* bs = (const float*)d_in[18];
    const float* ms = (const float*)d_in[19];
    const float* vs = (const float*)d_in[20];

    cudaFuncSetAttribute(k_conv3, cudaFuncAttributeMaxDynamicSharedMemorySize, C3_SMEM);

    k_reset<<<1, 32>>>();
    k_maxx<<<512, 256>>>(x);
    k_prep<<<8, 256>>>(w1, w2, w3, ws, g1, b1, m1, v1, g2, b2, m2, v2,
                       g3, b3, m3, v3, gs, bs, ms, vs);
    k_qx<<<1568, 256>>>(x);
    k_conv1<<<dim3(784, 3), 256>>>();
    k_conv2<<<1568, 384>>>();
    k_conv3<<<1568, 256, C3_SMEM>>>();
    k_convS<<<1568, 256>>>();
    k_epi<<<4704, 256>>>((float*)d_out);
}

// round 17
// speedup vs baseline: 2.0659x; 1.0020x over previous
#include <cuda_runtime.h>
#include <cstdint>

typedef unsigned int u32;
typedef unsigned short u16;
typedef signed char  s8;
typedef unsigned char u8;

#define HW    3136            // 56*56
#define NPIX  100352          // 32*3136
#define CIN   64
#define PEXP  384
#define COUT  96

// ---------------- device scratch ----------------
static __device__ __align__(16) s8    g_xq [(size_t)NPIX * CIN];      // x int4 codes, NHWC (s8)
static __device__ __align__(16) u8    g_o1 [(size_t)NPIX * (PEXP/2)]; // stage1 codes, 2/byte
static __device__ __align__(16) u8    g_o2 [(size_t)NPIX * (PEXP/2)]; // stage2 codes, 2/byte
static __device__ __align__(16) short g_acc3[(size_t)32 * COUT * HW]; // conv3 raw int acc, NCHW
static __device__ __align__(16) short g_accS[(size_t)32 * COUT * HW]; // shortcut raw int acc, NCHW
static __device__ __align__(16) s8    g_w1q[PEXP * CIN];
static __device__ __align__(16) s8    g_w2q[9 * PEXP];                // [tap][384]
static __device__ __align__(16) s8    g_w3q[COUT * PEXP];
static __device__ __align__(16) s8    g_wsq[COUT * CIN];
static __device__ float g_inv1[PEXP], g_add1[PEXP], g_inv2[PEXP], g_add2[PEXP];
static __device__ float g_inv3[COUT], g_add3[COUT], g_invS[COUT], g_addS[COUT];
static __device__ u32   g_maxx_bits;
static __device__ int   g_max_o1, g_max_o2, g_max_a3, g_max_aS;
static __device__ float g_sw[4];                 // s_w1, s_w2, s_w3, s_ws

// ---------------- helpers ----------------
__device__ __forceinline__ float pow2ceil(float q) {
    // exact exp2(ceil(log2(q))), q > 0
    int e; float f = frexpf(q, &e);     // q = f * 2^e, f in [0.5, 1)
    if (f == 0.5f) e -= 1;
    return ldexpf(1.0f, e);
}
__device__ __forceinline__ float load_sx() {
    // uniform recompute of s_x from the global max bits (identical ops everywhere)
    float m = fmaxf(__uint_as_float(g_maxx_bits), 1e-8f);
    return pow2ceil(__fdiv_rn(m, 7.0f));
}
__device__ __forceinline__ int clampi(int v, int lo, int hi) {
    return min(max(v, lo), hi);
}
__device__ __forceinline__ int wredmax(int v) {
    #pragma unroll
    for (int o = 16; o; o >>= 1) v = max(v, __shfl_xor_sync(0xffffffffu, v, o));
    return v;
}

// int8 tensor-core MMA: D(16x8,s32) += A(16x32,s8 row) * B(32x8,s8 col)
__device__ __forceinline__ void mma_s8(int& c0, int& c1, int& c2, int& c3,
                                       int a0, int a1, int a2, int a3,
                                       int b0, int b1) {
    asm volatile(
        "mma.sync.aligned.m16n8k32.row.col.s32.s8.s8.s32 "
        "{%0,%1,%2,%3},{%4,%5,%6,%7},{%8,%9},{%0,%1,%2,%3};"
        : "+r"(c0), "+r"(c1), "+r"(c2), "+r"(c3)
        : "r"(a0), "r"(a1), "r"(a2), "r"(a3), "r"(b0), "r"(b1));
}

// 256-entry requant LUT: index = packed byte (lo nibble = even channel code,
// hi nibble = odd channel code); value = mapped(lo) | mapped(hi)<<8 (both 0..7).
__device__ __forceinline__ void build_pairlut(u32* slut2, int t, int maxcode) {
    float m = fmaxf(__fmul_rn((float)maxcode, 0.25f), 1e-8f);
    float s = pow2ceil(__fdiv_rn(m, 7.0f));
    float si = 1.0f / s;
    if (t < 256) {
        int c0 = t & 15, c1 = t >> 4;
        int v0 = (int)fminf(fmaxf(rintf(__fmul_rn(__fmul_rn((float)c0, 0.25f), si)), -8.f), 7.f);
        int v1 = (int)fminf(fmaxf(rintf(__fmul_rn(__fmul_rn((float)c1, 0.25f), si)), -8.f), 7.f);
        slut2[t] = (u32)(v0 | (v1 << 8));
    }
}
// Unpack+map one packed word (8 codes) -> two unpacked s8 words (8 mapped values)
__device__ __forceinline__ void unmap_word(u32 w, const u32* slut2, u32& lo, u32& hi) {
    lo = slut2[w & 255u] | (slut2[(w >> 8) & 255u] << 16);
    hi = slut2[(w >> 16) & 255u] | (slut2[w >> 24] << 16);
}
__device__ __forceinline__ void unmap_int4(int4 v, const u32* slut2, int4& o0, int4& o1) {
    u32 a, b;
    unmap_word((u32)v.x, slut2, a, b); o0.x = (int)a; o0.y = (int)b;
    unmap_word((u32)v.y, slut2, a, b); o0.z = (int)a; o0.w = (int)b;
    unmap_word((u32)v.z, slut2, a, b); o1.x = (int)a; o1.y = (int)b;
    unmap_word((u32)v.w, slut2, a, b); o1.z = (int)a; o1.w = (int)b;
}

// ---------------- K0: reset atomics ----------------
__global__ void k_reset() {
    if (threadIdx.x == 0) {
        g_maxx_bits = 0u; g_max_o1 = 0; g_max_o2 = 0; g_max_a3 = 0; g_max_aS = 0;
    }
}

// ---------------- K1: max|x| (blocks 0..511) + weight quant / BN folds (512..518)
__global__ __launch_bounds__(256) void k_maxx_prep(
    const float* __restrict__ x,
    const float* __restrict__ w1, const float* __restrict__ w2,
    const float* __restrict__ w3, const float* __restrict__ ws,
    const float* __restrict__ g1, const float* __restrict__ b1,
    const float* __restrict__ m1, const float* __restrict__ v1,
    const float* __restrict__ g2, const float* __restrict__ b2,
    const float* __restrict__ m2, const float* __restrict__ v2,
    const float* __restrict__ g3, const float* __restrict__ b3,
    const float* __restrict__ m3, const float* __restrict__ v3,
    const float* __restrict__ gs, const float* __restrict__ bs,
    const float* __restrict__ ms, const float* __restrict__ vs) {
    const int t = threadIdx.x;
    if (blockIdx.x < 512) {
        __shared__ float sred8[8];
        float mx = 0.f;
        const int n4 = (32 * CIN * HW) / 4;
        for (int i = blockIdx.x * blockDim.x + t; i < n4; i += 512 * blockDim.x) {
            float4 v = ((const float4*)x)[i];
            mx = fmaxf(mx, fmaxf(fmaxf(fabsf(v.x), fabsf(v.y)), fmaxf(fabsf(v.z), fabsf(v.w))));
        }
        #pragma unroll
        for (int o = 16; o; o >>= 1) mx = fmaxf(mx, __shfl_xor_sync(0xffffffffu, mx, o));
        if ((t & 31) == 0) sred8[t >> 5] = mx;
        __syncthreads();
        if (t == 0) {
            float m = sred8[0];
            #pragma unroll
            for (int w = 1; w < 8; w++) m = fmaxf(m, sred8[w]);
            atomicMax(&g_maxx_bits, __float_as_uint(m));
        }
        return;
    }
    const int blk = blockIdx.x - 512;
    if (blk < 4) {
        const float* w; int n; s8* dst;
        if (blk == 0)      { w = w1; n = PEXP * CIN;  dst = g_w1q; }
        else if (blk == 1) { w = w2; n = PEXP * 9;    dst = g_w2q; }
        else if (blk == 2) { w = w3; n = COUT * PEXP; dst = g_w3q; }
        else               { w = ws; n = COUT * CIN;  dst = g_wsq; }
        __shared__ float sred[256];
        __shared__ float s_si;
        float mx = 0.f;
        for (int i = t; i < n; i += 256) mx = fmaxf(mx, fabsf(w[i]));
        sred[t] = mx; __syncthreads();
        for (int s = 128; s > 0; s >>= 1) {
            if (t < s) sred[t] = fmaxf(sred[t], sred[t + s]);
            __syncthreads();
        }
        if (t == 0) {
            float m = fmaxf(sred[0], 1e-8f);
            float s = pow2ceil(__fdiv_rn(m, 7.0f));
            g_sw[blk] = s; s_si = 1.0f / s;
        }
        __syncthreads();
        float si = s_si;
        for (int i = t; i < n; i += 256) {
            float r = fminf(fmaxf(rintf(__fmul_rn(w[i], si)), -8.f), 7.f);
            if (blk == 1) { int p = i / 9, tap = i % 9; g_w2q[tap * PEXP + p] = (s8)(int)r; }
            else dst[i] = (s8)(int)r;
        }
    } else if (blk == 4) {
        for (int c = t; c < PEXP; c += 256) {
            float inv = __fmul_rn(g1[c], 1.0f / sqrtf(v1[c] + 1e-5f));
            g_inv1[c] = inv; g_add1[c] = __fsub_rn(b1[c], __fmul_rn(m1[c], inv));
        }
    } else if (blk == 5) {
        for (int c = t; c < PEXP; c += 256) {
            float inv = __fmul_rn(g2[c], 1.0f / sqrtf(v2[c] + 1e-5f));
            g_inv2[c] = inv; g_add2[c] = __fsub_rn(b2[c], __fmul_rn(m2[c], inv));
        }
    } else {
        for (int c = t; c < COUT; c += 256) {
            float inv = __fmul_rn(g3[c], 1.0f / sqrtf(v3[c] + 1e-5f));
            g_inv3[c] = inv; g_add3[c] = __fsub_rn(b3[c], __fmul_rn(m3[c], inv));
            float invs = __fmul_rn(gs[c], 1.0f / sqrtf(vs[c] + 1e-5f));
            g_invS[c] = invs; g_addS[c] = __fsub_rn(bs[c], __fmul_rn(ms[c], invs));
        }
    }
}

// ---------------- K2: quantize x, NCHW f32 -> NHWC int8 codes (LDG.128) -------
__global__ __launch_bounds__(256) void k_qx(const float* __restrict__ x) {
    __shared__ s8 sm[64 * 68];
    const int b = blockIdx.x / 49;
    const int pix0 = (blockIdx.x % 49) * 64;          // within-image pixel base
    const int t = threadIdx.x;
    const float sxinv = 1.0f / load_sx();
    #pragma unroll
    for (int j = 0; j < 4; j++) {
        int idx = t + 256 * j;                         // 0..1023
        int c = idx >> 4, f4 = idx & 15;
        const float4 v = *(const float4*)(x + (size_t)(b * CIN + c) * HW + pix0 + f4 * 4);
        const float* vp = (const float*)&v;
        #pragma unroll
        for (int k = 0; k < 4; k++) {
            float q = fminf(fmaxf(rintf(__fmul_rn(vp[k], sxinv)), -8.f), 7.f);
            sm[(f4 * 4 + k) * 68 + c] = (s8)(int)q;
        }
    }
    __syncthreads();
    const int pix = t >> 2, cofs = (t & 3) * 16;
    const int* sp = (const int*)(sm + pix * 68 + cofs);
    int4 v = make_int4(sp[0], sp[1], sp[2], sp[3]);
    ((int4*)g_xq)[(size_t)(b * HW + pix0 + pix) * 4 + (t & 3)] = v;
}

// ---------------- K3: conv1 1x1 (64->384) via mma.s8 + BN + relu4 ------------
// Block: 128 pixels x 128 outs. Grid (784, 3). Packed nibble output.
__global__ __launch_bounds__(256) void k_conv1() {
    __shared__ s8 As[128 * 80];        // 128 pix x 64 k, rows padded to 80B
    __shared__ s8 Bs[128 * 80];        // 128 out x 64 k
    __shared__ u8 so[128 * 112];       // packed staging: 64 bytes/pixel, rows padded to 112B
    __shared__ float sInv[128], sAdd[128];
    __shared__ int s_wmax[8];
    const int pix0 = blockIdx.x * 128;
    const int p0   = blockIdx.y * 128;
    const int t = threadIdx.x;
    const int4* xg = (const int4*)g_xq;
    const int4* wg = (const int4*)g_w1q;
    #pragma unroll
    for (int i = t; i < 512; i += 256) {
        int pix = i >> 2, q = i & 3;
        *(int4*)(As + pix * 80 + q * 16) = xg[(size_t)(pix0 + pix) * 4 + q];
    }
    #pragma unroll
    for (int i = t; i < 512; i += 256) {
        int o = i >> 2, q = i & 3;
        *(int4*)(Bs + o * 80 + q * 16) = wg[(p0 + o) * 4 + q];
    }
    if (t < 128) { sInv[t] = g_inv1[p0 + t]; sAdd[t] = g_add1[p0 + t]; }
    __syncthreads();
    const int w = t >> 5, l = t & 31, g = l >> 2, t4 = l & 3;
    const int wp0 = w * 16;
    int a[2][4];
    #pragma unroll
    for (int ki = 0; ki < 2; ki++) {
        a[ki][0] = *(const int*)(As + (wp0 + g) * 80 + ki * 32 + 4 * t4);
        a[ki][1] = *(const int*)(As + (wp0 + g + 8) * 80 + ki * 32 + 4 * t4);
        a[ki][2] = *(const int*)(As + (wp0 + g) * 80 + ki * 32 + 16 + 4 * t4);
        a[ki][3] = *(const int*)(As + (wp0 + g + 8) * 80 + ki * 32 + 16 + 4 * t4);
    }
    int c[16][4];
    #pragma unroll
    for (int nf = 0; nf < 16; nf++) { c[nf][0] = c[nf][1] = c[nf][2] = c[nf][3] = 0; }
    #pragma unroll
    for (int ki = 0; ki < 2; ki++)
        #pragma unroll
        for (int nf = 0; nf < 16; nf++) {
            int b0 = *(const int*)(Bs + (nf * 8 + g) * 80 + ki * 32 + 4 * t4);
            int b1 = *(const int*)(Bs + (nf * 8 + g) * 80 + ki * 32 + 16 + 4 * t4);
            mma_s8(c[nf][0], c[nf][1], c[nf][2], c[nf][3],
                   a[ki][0], a[ki][1], a[ki][2], a[ki][3], b0, b1);
        }
    const float sc = __fmul_rn(load_sx(), g_sw[0]);
    int mymax = 0;
    #pragma unroll
    for (int nf = 0; nf < 16; nf++) {
        int ob = nf * 8 + 2 * t4;          // even channel of the pair
        float inv0 = sInv[ob], add0 = sAdd[ob];
        float inv1 = sInv[ob + 1], add1 = sAdd[ob + 1];
        #pragma unroll
        for (int i = 0; i < 2; i++) {
            int pix = wp0 + g + 8 * i;
            float r0 = __fmul_rn(__int2float_rn(c[nf][2 * i]), sc);
            float y0 = __fadd_rn(__fmul_rn(r0, inv0), add0);
            int q0 = clampi((int)rintf(__fmul_rn(y0, 4.0f)), 0, 15);
            float r1 = __fmul_rn(__int2float_rn(c[nf][2 * i + 1]), sc);
            float y1 = __fadd_rn(__fmul_rn(r1, inv1), add1);
            int q1 = clampi((int)rintf(__fmul_rn(y1, 4.0f)), 0, 15);
            mymax = max(mymax, max(q0, q1));
            so[pix * 112 + (ob >> 1)] = (u8)(q0 | (q1 << 4));   // lo nibble = even ch
        }
    }
    mymax = wredmax(mymax);
    if (l == 0) s_wmax[w] = mymax;
    __syncthreads();
    // copy packed staging (64B/pixel) to global (192B/pixel rows, offset p0/2)
    #pragma unroll
    for (int i = t; i < 512; i += 256) {
        int pix = i >> 2, c16 = i & 3;
        ((int4*)g_o1)[(size_t)(pix0 + pix) * 12 + (p0 >> 5) + c16] =
            *(const int4*)(so + pix * 112 + c16 * 16);
    }
    if (t == 0) {
        int m = s_wmax[0];
        #pragma unroll
        for (int ww = 1; ww < 8; ww++) m = max(m, s_wmax[ww]);
        atomicMax(&g_max_o1, m);
    }
}

// ---------------- K4: depthwise 3x3 + BN + relu4 (packed in/out, map on load) --
__global__ __launch_bounds__(384) void k_conv2() {
    __shared__ s8 sm[10 * 10 * PEXP];      // 38400 B (unpacked mapped s8)
    __shared__ u32 slut2[256];
    __shared__ int s_wmax[12];
    const int b = blockIdx.x / 49;
    const int tile = blockIdx.x % 49;
    const int oy0 = (tile / 7) * 8, ox0 = (tile % 7) * 8;
    const int t = threadIdx.x;
    build_pairlut(slut2, t, g_max_o1);
    float s2p;
    {
        float m = fmaxf(__fmul_rn((float)g_max_o1, 0.25f), 1e-8f);
        float s = pow2ceil(__fdiv_rn(m, 7.0f));
        s2p = __fmul_rn(s, g_sw[1]);
    }
    __syncthreads();   // slut2 ready
    for (int idx = t; idx < 1200; idx += 384) {
        int cell = idx / 12, q = idx % 12;
        int iy = oy0 - 1 + cell / 10, ix = ox0 - 1 + cell % 10;
        int4 o0 = make_int4(0, 0, 0, 0), o1 = make_int4(0, 0, 0, 0);
        if (iy >= 0 && iy < 56 && ix >= 0 && ix < 56) {
            int4 v = ((const int4*)g_o1)[(size_t)(b * HW + iy * 56 + ix) * 12 + q];
            unmap_int4(v, slut2, o0, o1);
        }
        ((int4*)sm)[cell * 24 + q * 2]     = o0;
        ((int4*)sm)[cell * 24 + q * 2 + 1] = o1;
    }
    __syncthreads();
    const int c4 = t % 96, strip = t / 96;
    int wl[9][4];                           // byte-isolated weights for dp4a
    #pragma unroll
    for (int tap = 0; tap < 9; tap++) {
        int w = ((const int*)g_w2q)[tap * 96 + c4];
        wl[tap][0] = w & 0x000000FF;
        wl[tap][1] = w & 0x0000FF00;
        wl[tap][2] = w & 0x00FF0000;
        wl[tap][3] = (int)((u32)w & 0xFF000000u);
    }
    float inv[4], add[4];
    #pragma unroll
    for (int l = 0; l < 4; l++) { int c = c4 * 4 + l; inv[l] = g_inv2[c]; add[l] = g_add2[c]; }
    int mymax = 0;
    #pragma unroll
    for (int sub = 0; sub < 4; sub++) {
        int base[4], oyv[4], oxv[4];
        #pragma unroll
        for (int k = 0; k < 4; k++) {
            int pix = strip * 16 + sub * 4 + k;
            int oy = pix >> 3, ox = pix & 7;
            oyv[k] = oy; oxv[k] = ox;
            base[k] = (oy * 10 + ox) * PEXP + c4 * 4;
        }
        int acc[4][4] = {};
        #pragma unroll
        for (int dy = 0; dy < 3; dy++)
            #pragma unroll
            for (int dx = 0; dx < 3; dx++) {
                int tap = dy * 3 + dx;
                int toff = (dy * 10 + dx) * PEXP;
                #pragma unroll
                for (int k = 0; k < 4; k++) {
                    int v = *(const int*)(sm + base[k] + toff);
                    acc[k][0] = __dp4a(v, wl[tap][0], acc[k][0]);
                    acc[k][1] = __dp4a(v, wl[tap][1], acc[k][1]);
                    acc[k][2] = __dp4a(v, wl[tap][2], acc[k][2]);
                    acc[k][3] = __dp4a(v, wl[tap][3], acc[k][3]);
                }
            }
        #pragma unroll
        for (int k = 0; k < 4; k++) {
            u32 pk = 0;
            #pragma unroll
            for (int l = 0; l < 4; l++) {
                float raw = __fmul_rn(__int2float_rn(acc[k][l]), s2p);
                float y = __fadd_rn(__fmul_rn(raw, inv[l]), add[l]);
                int code = clampi((int)rintf(__fmul_rn(y, 4.0f)), 0, 15);
                mymax = max(mymax, code);
                pk |= (u32)code << (4 * l);           // pack 4 codes into 2 bytes
            }
            *(u16*)(g_o2 + (size_t)(b * HW + (oy0 + oyv[k]) * 56 + (ox0 + oxv[k])) * (PEXP/2) + c4 * 2) = (u16)pk;
        }
    }
    mymax = wredmax(mymax);
    if ((t & 31) == 0) s_wmax[t >> 5] = mymax;
    __syncthreads();
    if (t == 0) {
        int m = s_wmax[0];
        #pragma unroll
        for (int w = 1; w < 12; w++) m = max(m, s_wmax[w]);
        atomicMax(&g_max_o2, m);
    }
}

// ---------------- K5: fused conv3 (384->96) + shortcut (64->96) via mma.s8 -----
// Block: 64 pixels. Dynamic smem layout:
#define C3_AS    0                     // 64 x 400
#define C3_BS    25600                 // 96 x 400
#define C3_SS    64000                 // 96 x 64 int16
#define C3_LUT   76288                 // 256 u32
#define C3_WMAX  77312                 // 8 int
#define CS_AS    77344                 // 64 x 80
#define CS_BS    82464                 // 96 x 80
#define C3_SMEM  90144
__global__ __launch_bounds__(256) void k_conv3S() {
    extern __shared__ char dsm[];
    s8*   As    = (s8*)(dsm + C3_AS);
    s8*   Bs    = (s8*)(dsm + C3_BS);
    short* ss   = (short*)(dsm + C3_SS);
    u32*  slut2 = (u32*)(dsm + C3_LUT);
    int*  s_wmax = (int*)(dsm + C3_WMAX);
    s8*   AsS   = (s8*)(dsm + CS_AS);
    s8*   BsS   = (s8*)(dsm + CS_BS);
    const int pix0 = blockIdx.x * 64;
    const int t = threadIdx.x;
    build_pairlut(slut2, t, g_max_o2);     // g_max_o2 final (conv2 done)
    __syncthreads();
    const int4* xg = (const int4*)g_o2;
    const int4* wg = (const int4*)g_w3q;
    const int4* xgS = (const int4*)g_xq;
    const int4* wgS = (const int4*)g_wsq;
    for (int i = t; i < 768; i += 256) {
        int pix = i / 12, q = i % 12;
        int4 o0, o1;
        unmap_int4(xg[(size_t)(pix0 + pix) * 12 + q], slut2, o0, o1);
        *(int4*)(As + pix * 400 + q * 32)      = o0;
        *(int4*)(As + pix * 400 + q * 32 + 16) = o1;
    }
    for (int i = t; i < 2304; i += 256) {
        int o = i / 24, q = i % 24;
        *(int4*)(Bs + o * 400 + q * 16) = wg[o * 24 + q];
    }
    if (t < 256) {
        int pix = t >> 2, q = t & 3;
        *(int4*)(AsS + pix * 80 + q * 16) = xgS[(size_t)(pix0 + pix) * 4 + q];
    }
    #pragma unroll
    for (int i = t; i < 384; i += 256) {
        int o = i >> 2, q = i & 3;
        *(int4*)(BsS + o * 80 + q * 16) = wgS[o * 4 + q];
    }
    __syncthreads();
    const int w = t >> 5, l = t & 31, g = l >> 2, t4 = l & 3;
    const int pg = w >> 1, oh = w & 1;
    const int prow = pg * 16, obase = oh * 48;
    const int bimg = pix0 / HW, hw0 = pix0 % HW;
    // ---- phase 1: conv3 (K=384) ----
    {
        int c[6][4];
        #pragma unroll
        for (int nf = 0; nf < 6; nf++) { c[nf][0] = c[nf][1] = c[nf][2] = c[nf][3] = 0; }
        #pragma unroll
        for (int ki = 0; ki < 12; ki++) {
            int a0 = *(const int*)(As + (prow + g) * 400 + ki * 32 + 4 * t4);
            int a1 = *(const int*)(As + (prow + g + 8) * 400 + ki * 32 + 4 * t4);
            int a2 = *(const int*)(As + (prow + g) * 400 + ki * 32 + 16 + 4 * t4);
            int a3 = *(const int*)(As + (prow + g + 8) * 400 + ki * 32 + 16 + 4 * t4);
            #pragma unroll
            for (int nf = 0; nf < 6; nf++) {
                int b0 = *(const int*)(Bs + (obase + nf * 8 + g) * 400 + ki * 32 + 4 * t4);
                int b1 = *(const int*)(Bs + (obase + nf * 8 + g) * 400 + ki * 32 + 16 + 4 * t4);
                mma_s8(c[nf][0], c[nf][1], c[nf][2], c[nf][3], a0, a1, a2, a3, b0, b1);
            }
        }
        int amax = 0;
        #pragma unroll
        for (int nf = 0; nf < 6; nf++)
            #pragma unroll
            for (int i = 0; i < 2; i++)
                #pragma unroll
                for (int j = 0; j < 2; j++) {
                    int a = c[nf][2 * i + j];
                    amax = max(amax, abs(a));
                    ss[(obase + nf * 8 + 2 * t4 + j) * 64 + (prow + g + 8 * i)] = (short)a;
                }
        amax = wredmax(amax);
        if (l == 0) s_wmax[w] = amax;
        __syncthreads();
        const int4* s4 = (const int4*)ss;
        #pragma unroll
        for (int i = t; i < 768; i += 256) {
            int o = i >> 3, seg = i & 7;
            ((int4*)g_acc3)[(size_t)(bimg * COUT + o) * 392 + (hw0 >> 3) + seg] = s4[i];
        }
        if (t == 0) {
            int m = s_wmax[0];
            #pragma unroll
            for (int ww = 1; ww < 8; ww++) m = max(m, s_wmax[ww]);
            atomicMax(&g_max_a3, m);
        }
    }
    __syncthreads();   // ss reads + s_wmax read done before reuse
    // ---- phase 2: shortcut (K=64) ----
    {
        int c[6][4];
        #pragma unroll
        for (int nf = 0; nf < 6; nf++) { c[nf][0] = c[nf][1] = c[nf][2] = c[nf][3] = 0; }
        #pragma unroll
        for (int ki = 0; ki < 2; ki++) {
            int a0 = *(const int*)(AsS + (prow + g) * 80 + ki * 32 + 4 * t4);
            int a1 = *(const int*)(AsS + (prow + g + 8) * 80 + ki * 32 + 4 * t4);
            int a2 = *(const int*)(AsS + (prow + g) * 80 + ki * 32 + 16 + 4 * t4);
            int a3 = *(const int*)(AsS + (prow + g + 8) * 80 + ki * 32 + 16 + 4 * t4);
            #pragma unroll
            for (int nf = 0; nf < 6; nf++) {
                int b0 = *(const int*)(BsS + (obase + nf * 8 + g) * 80 + ki * 32 + 4 * t4);
                int b1 = *(const int*)(BsS + (obase + nf * 8 + g) * 80 + ki * 32 + 16 + 4 * t4);
                mma_s8(c[nf][0], c[nf][1], c[nf][2], c[nf][3], a0, a1, a2, a3, b0, b1);
            }
        }
        int amax = 0;
        #pragma unroll
        for (int nf = 0; nf < 6; nf++)
            #pragma unroll
            for (int i = 0; i < 2; i++)
                #pragma unroll
                for (int j = 0; j < 2; j++) {
                    int a0 = c[nf][2 * i + j];
                    amax = max(amax, abs(a0));
                    ss[(obase + nf * 8 + 2 * t4 + j) * 64 + (prow + g + 8 * i)] = (short)a0;
                }
        amax = wredmax(amax);
        if (l == 0) s_wmax[w] = amax;
        __syncthreads();
        const int4* s4 = (const int4*)ss;
        #pragma unroll
        for (int i = t; i < 768; i += 256) {
            int o = i >> 3, seg = i & 7;
            ((int4*)g_accS)[(size_t)(bimg * COUT + o) * 392 + (hw0 >> 3) + seg] = s4[i];
        }
        if (t == 0) {
            int m = s_wmax[0];
            #pragma unroll
            for (int ww = 1; ww < 8; ww++) m = max(m, s_wmax[ww]);
            atomicMax(&g_max_aS, m);
        }
    }
}

// ---------------- K6: fused epilogue (scales computed inline) -> output --------
__global__ __launch_bounds__(256) void k_epi(float* __restrict__ out) {
    float m2 = fmaxf(__fmul_rn((float)g_max_o2, 0.25f), 1e-8f);
    float s2 = pow2ceil(__fdiv_rn(m2, 7.0f));
    float s3prod = __fmul_rn(s2, g_sw[2]);
    float m3 = fmaxf(__fmul_rn(s3prod, (float)g_max_a3), 1e-8f);
    float sO = pow2ceil(__fdiv_rn(m3, 127.0f));
    float r3 = __fdiv_rn(s3prod, sO);
    float sxw = __fmul_rn(load_sx(), g_sw[3]);
    float mS = fmaxf(__fmul_rn(sxw, (float)g_max_aS), 1e-8f);
    float sS = pow2ceil(__fdiv_rn(mS, 7.0f));
    float rS = __fdiv_rn(sxw, sS);
    const int n8 = (32 * COUT * HW) / 8;   // 1204224
    for (int i = blockIdx.x * blockDim.x + threadIdx.x; i < n8; i += gridDim.x * blockDim.x) {
        int c = (i / 392) % COUT;
        float inv3 = g_inv3[c], add3 = g_add3[c], invS = g_invS[c], addS = g_addS[c];
        int4 av = ((const int4*)g_acc3)[i];
        int4 sv = ((const int4*)g_accS)[i];
        const short* ap = (const short*)&av;
        const short* sp = (const short*)&sv;
        float r[8];
        #pragma unroll
        for (int l = 0; l < 8; l++) {
            float q3 = fminf(fmaxf(rintf(__fmul_rn((float)ap[l], r3)), -128.f), 127.f);
            float y3 = __fadd_rn(__fmul_rn(__fmul_rn(q3, sO), inv3), add3);
            float qS = fminf(fmaxf(rintf(__fmul_rn((float)sp[l], rS)), -8.f), 7.f);
            float yS = __fadd_rn(__fmul_rn(__fmul_rn(qS, sS), invS), addS);
            float sum = __fadd_rn(y3, yS);
            float code = fminf(fmaxf(rintf(__fmul_rn(sum, 4.0f)), 0.f), 15.f);
            r[l] = __fmul_rn(code, 0.25f);
        }
        float4* o4 = (float4*)out;
        o4[(size_t)i * 2]     = make_float4(r[0], r[1], r[2], r[3]);
        o4[(size_t)i * 2 + 1] = make_float4(r[4], r[5], r[6], r[7]);
    }
}

// ---------------- launch ----------------
extern "C" void kernel_launch(void* const* d_in, const int* in_sizes, int n_in,
                              void* d_out, int out_size) {
    const float* x  = (const float*)d_in[0];
    const float* w1 = (const float*)d_in[1];
    const float* g1 = (const float*)d_in[2];
    const float* b1 = (const float*)d_in[3];
    const float* m1 = (const float*)d_in[4];
    const float* v1 = (const float*)d_in[5];
    const float* w2 = (const float*)d_in[6];
    const float* g2 = (const float*)d_in[7];
    const float* b2 = (const float*)d_in[8];
    const float* m2 = (const float*)d_in[9];
    const float* v2 = (const float*)d_in[10];
    const float* w3 = (const float*)d_in[11];
    const float* g3 = (const float*)d_in[12];
    const float* b3 = (const float*)d_in[13];
    const float* m3 = (const float*)d_in[14];
    const float* v3 = (const float*)d_in[15];
    const float* ws = (const float*)d_in[16];
    const float* gs = (const float*)d_in[17];
    const float* bs = (const float*)d_in[18];
    const float* ms = (const float*)d_in[19];
    const float* vs = (const float*)d_in[20];

    cudaFuncSetAttribute(k_conv3S, cudaFuncAttributeMaxDynamicSharedMemorySize, C3_SMEM);

    k_reset<<<1, 32>>>();
    k_maxx_prep<<<519, 256>>>(x, w1, w2, w3, ws, g1, b1, m1, v1, g2, b2, m2, v2,
                              g3, b3, m3, v3, gs, bs, ms, vs);
    k_qx<<<1568, 256>>>(x);
    k_conv1<<<dim3(784, 3), 256>>>();
    k_conv2<<<1568, 384>>>();
    k_conv3S<<<1568, 256, C3_SMEM>>>();
    k_epi<<<4704, 256>>>((float*)d_out);
}